// round 10
// baseline (speedup 1.0000x reference)
#include <cuda_runtime.h>
#include <math.h>
#include <stdint.h>

// Problem constants
#define BB 4
#define LL 1024
#define DD 1024
#define HH 16
#define HD 64
#define EE 16384
#define D3 3072

#define NEGF (-1e30f)

// ---------------------------------------------------------------------------
// Scratch (static device globals; no allocation allowed)
// ---------------------------------------------------------------------------
__device__ float g_q[(size_t)BB * HH * LL * HD];   // [B,H,L,HD], tf32, q*0.125
__device__ float g_k[(size_t)BB * HH * LL * HD];   // [B,H,L,HD], tf32, d-interleaved
__device__ float g_v[(size_t)BB * HH * LL * HD];   // [B,H,L,HD], tf32, normal
__device__ float g_attn[(size_t)BB * LL * DD];     // [B,L,D], tf32, d-interleaved
__device__ unsigned g_adj[LL * (LL / 32)];         // bitmask

// tf32-rounded, k-interleaved copies of GEMM operands
__device__ float g_xc[(size_t)BB * LL * DD];       // x     [4096,1024]
__device__ float g_wq[(size_t)D3 * DD];            // w_qkv [3072,1024]
__device__ float g_wo[(size_t)DD * DD];            // w_out [1024,1024]

// ---------------------------------------------------------------------------
// Helpers
// ---------------------------------------------------------------------------
__device__ __forceinline__ unsigned f2tf32(float f) {
    unsigned u;
    asm("cvt.rna.tf32.f32 %0, %1;" : "=r"(u) : "f"(f));
    return u;
}

__device__ __forceinline__ void mma_tf32(float* d, const unsigned* a,
                                         unsigned b0, unsigned b1) {
    asm volatile(
        "mma.sync.aligned.m16n8k8.row.col.f32.tf32.tf32.f32 "
        "{%0,%1,%2,%3}, {%4,%5,%6,%7}, {%8,%9}, {%0,%1,%2,%3};"
        : "+f"(d[0]), "+f"(d[1]), "+f"(d[2]), "+f"(d[3])
        : "r"(a[0]), "r"(a[1]), "r"(a[2]), "r"(a[3]), "r"(b0), "r"(b1));
}

__device__ __forceinline__ uint32_t smem_u32(const void* p) {
    uint32_t a;
    asm("{ .reg .u64 t; cvta.to.shared.u64 t, %1; cvt.u32.u64 %0, t; }"
        : "=r"(a) : "l"(p));
    return a;
}

__device__ __forceinline__ void cp_async16(uint32_t saddr, const void* gptr) {
    asm volatile("cp.async.cg.shared.global [%0], [%1], 16;"
                 :: "r"(saddr), "l"(gptr) : "memory");
}
__device__ __forceinline__ void cp_commit() {
    asm volatile("cp.async.commit_group;" ::: "memory");
}
template <int N>
__device__ __forceinline__ void cp_wait() {
    asm volatile("cp.async.wait_group %0;" :: "n"(N) : "memory");
}

// ---------------------------------------------------------------------------
// Kernel 1: adjacency
// ---------------------------------------------------------------------------
__global__ void adj_clear_k() {
    int i = blockIdx.x * blockDim.x + threadIdx.x;
    if (i < LL * (LL / 32)) g_adj[i] = 0u;
}

__global__ void adj_scatter_k(const int* __restrict__ edges) {
    int e = blockIdx.x * blockDim.x + threadIdx.x;
    if (e >= EE) return;
    int a = edges[2 * e + 0];
    int b = edges[2 * e + 1];
    atomicOr(&g_adj[a * 32 + (b >> 5)], 1u << (b & 31));
    atomicOr(&g_adj[b * 32 + (a >> 5)], 1u << (a & 31));
}

// ---------------------------------------------------------------------------
// Kernel 2: tf32 conversion + 8-group column interleave.
// For each group of 8 along the last dim, store order [0,4,1,5,2,6,3,7]
// (out[p] = in[perm[p]]), so cols (c, c+4) sit adjacent -> LDS.64 fragments.
// ---------------------------------------------------------------------------
__global__ void conv_tf32_il_k(const float* __restrict__ in,
                               float* __restrict__ out, int n8) {
    int i = blockIdx.x * blockDim.x + threadIdx.x;
    if (i >= n8) return;
    const float* s = in + (size_t)i * 8;
    float* d = out + (size_t)i * 8;
    float4 a = *(const float4*)s;
    float4 b = *(const float4*)(s + 4);
    *(uint4*)d       = make_uint4(f2tf32(a.x), f2tf32(b.x), f2tf32(a.y), f2tf32(b.y));
    *(uint4*)(d + 4) = make_uint4(f2tf32(a.z), f2tf32(b.z), f2tf32(a.w), f2tf32(b.w));
}

// interleave position of low-3-bits r within its 8-group
__device__ __forceinline__ int il8(int r) {
    return ((r & 3) << 1) | ((r >> 2) & 1);
}

// ---------------------------------------------------------------------------
// TF32 tensor-core GEMM v3: C[m,n] = sum_k A[m,k]*Bm[n,k] + bias[n]
// Operands pre-rounded to tf32 and k-interleaved -> raw cp.async staging,
// LDS.64 fragment loads. BM=BN=128, BK=32, 8 warps, warp tile 64x32.
// Smem stride 40 floats: 64-bit frag loads conflict-free (4g+t mod 16).
// MODE 1: A=g_xc, B=g_wq -> scatter Q/K/V (K d-interleaved), q*0.125
// MODE 0: A=g_attn, B=g_wo -> Cout row-major (+bias)
// ---------------------------------------------------------------------------
#define SSTR 40
#define GSTG (128 * SSTR)                 // floats per matrix per stage
#define GEMM_SMEM (4 * GSTG * 4)          // 81920 bytes

template <int MODE>
__global__ void __launch_bounds__(256, 2) gemm_k(const float* __restrict__ bias,
                                                 float* __restrict__ Cout) {
    constexpr int K = 1024;
    const float* A  = (MODE == 1) ? g_xc : g_attn;
    const float* Bm = (MODE == 1) ? g_wq : g_wo;

    extern __shared__ float sm[];
    const int tid = threadIdx.x;
    const int m0 = blockIdx.y * 128;
    const int n0 = blockIdx.x * 128;

    const int lrow = tid >> 1;
    const int lk   = (tid & 1) * 16;
    const float* Ag = A  + (size_t)(m0 + lrow) * K + lk;
    const float* Bg = Bm + (size_t)(n0 + lrow) * K + lk;
    const uint32_t sA = smem_u32(sm) + (lrow * SSTR + lk) * 4;

    const int wid  = tid >> 5;
    const int lane = tid & 31;
    const int wm   = (wid & 1) * 64;
    const int wn   = (wid >> 1) * 32;
    const int g    = lane >> 2;
    const int t    = lane & 3;

    float acc[4][4][4];
#pragma unroll
    for (int mi = 0; mi < 4; mi++)
#pragma unroll
        for (int ni = 0; ni < 4; ni++)
#pragma unroll
            for (int e = 0; e < 4; e++) acc[mi][ni][e] = 0.f;

    // Prologue: stage k-tiles 0,1
#pragma unroll
    for (int pt = 0; pt < 2; pt++) {
        const uint32_t base = sA + pt * 2 * GSTG * 4;
        const float* ag = Ag + pt * 32;
        const float* bg = Bg + pt * 32;
#pragma unroll
        for (int i = 0; i < 4; i++) {
            cp_async16(base + i * 16, ag + 4 * i);
            cp_async16(base + GSTG * 4 + i * 16, bg + 4 * i);
        }
        cp_commit();
    }

#pragma unroll 1
    for (int it = 0; it < 32; it++) {
        const int s = it & 1;
        if (it < 31) cp_wait<1>(); else cp_wait<0>();
        __syncthreads();

        const float* Asm = sm + s * 2 * GSTG;
        const float* Bsm = Asm + GSTG;

#pragma unroll
        for (int ks = 0; ks < 4; ks++) {
            const int kb2 = ks * 8 + 2 * t;
            unsigned af[4][4];
#pragma unroll
            for (int mi = 0; mi < 4; mi++) {
                const int r = wm + mi * 16 + g;
                uint2 a0 = *(const uint2*)(Asm + r * SSTR + kb2);
                uint2 a1 = *(const uint2*)(Asm + (r + 8) * SSTR + kb2);
                af[mi][0] = a0.x; af[mi][1] = a1.x;
                af[mi][2] = a0.y; af[mi][3] = a1.y;
            }
            uint2 bf[4];
#pragma unroll
            for (int ni = 0; ni < 4; ni++) {
                const int c = wn + ni * 8 + g;
                bf[ni] = *(const uint2*)(Bsm + c * SSTR + kb2);
            }
#pragma unroll
            for (int mi = 0; mi < 4; mi++)
#pragma unroll
                for (int ni = 0; ni < 4; ni++)
                    mma_tf32(acc[mi][ni], af[mi], bf[ni].x, bf[ni].y);
        }

        __syncthreads();
        if (it + 2 < 32) {
            const uint32_t base = sA + s * 2 * GSTG * 4;
            const float* ag = Ag + (it + 2) * 32;
            const float* bg = Bg + (it + 2) * 32;
#pragma unroll
            for (int i = 0; i < 4; i++) {
                cp_async16(base + i * 16, ag + 4 * i);
                cp_async16(base + GSTG * 4 + i * 16, bg + 4 * i);
            }
            cp_commit();
        }
    }

    const int g2t = 2 * t;
    if (MODE == 1) {
        const int part = n0 >> 10;   // 128-tile never crosses a 1024 boundary
        float* dstbase = (part == 0) ? g_q : (part == 1) ? g_k : g_v;
        const float qs = (part == 0) ? 0.125f : 1.0f;
        const int i0 = il8(g2t);         // K interleave targets
        const int i1 = il8(g2t + 1);
#pragma unroll
        for (int mi = 0; mi < 4; mi++) {
#pragma unroll
            for (int half = 0; half < 2; half++) {
                const int m  = m0 + wm + mi * 16 + g + half * 8;
                const int bb = m >> 10;
                const int ll = m & 1023;
#pragma unroll
                for (int ni = 0; ni < 4; ni++) {
                    const int col = n0 + wn + ni * 8 + g2t;
                    const int nn  = col & 1023;
                    const int h   = nn >> 6;
                    const int d   = nn & 63;
                    float v0 = __uint_as_float(f2tf32((acc[mi][ni][half * 2 + 0] + bias[col]) * qs));
                    float v1 = __uint_as_float(f2tf32((acc[mi][ni][half * 2 + 1] + bias[col + 1]) * qs));
                    float* p = dstbase +
                               (((size_t)bb * HH + h) * LL + ll) * HD + (d & ~7);
                    if (part == 1) {        // K: d-interleaved for LDS.64 frags
                        p[i0] = v0;
                        p[i1] = v1;
                    } else {                // Q,V: normal layout
                        p[(d & 7)]     = v0;
                        p[(d & 7) + 1] = v1;
                    }
                }
            }
        }
    } else {
#pragma unroll
        for (int mi = 0; mi < 4; mi++) {
#pragma unroll
            for (int half = 0; half < 2; half++) {
                const int m = m0 + wm + mi * 16 + g + half * 8;
#pragma unroll
                for (int ni = 0; ni < 4; ni++) {
                    const int col = n0 + wn + ni * 8 + g2t;
                    float* p = Cout + (size_t)m * DD + col;
                    p[0] = acc[mi][ni][half * 2 + 0] + bias[col];
                    p[1] = acc[mi][ni][half * 2 + 1] + bias[col + 1];
                }
            }
        }
    }
}

// ---------------------------------------------------------------------------
// Kernel 3: tensor-core masked flash attention, v4.
// v4: K smem stride 72 with d-interleaved columns -> QK fragments are one
// LDS.64 each (halves K fragment LDS). cp.async double-buffered staging.
// Epilogue writes g_attn tf32-rounded AND d-interleaved (out-proj A operand).
// ---------------------------------------------------------------------------
#define KS_STR 72
#define VS_STR 72
#define STAGE_W (64 * (KS_STR + VS_STR))          // floats per stage
#define ATTN_SMEM (2 * STAGE_W * 4)               // 73728 bytes

__global__ void __launch_bounds__(256, 2) attn_mma_k() {
    extern __shared__ float sm[];

    const int bh   = blockIdx.y;
    const int tid  = threadIdx.x;
    const int wid  = tid >> 5;
    const int lane = tid & 31;
    const int g    = lane >> 2;
    const int t    = lane & 3;
    const int q0   = blockIdx.x * 128;
    const int wrow = wid * 16;

    const float* Qg = g_q + (size_t)bh * LL * HD;
    const float* Kg = g_k + (size_t)bh * LL * HD;
    const float* Vg = g_v + (size_t)bh * LL * HD;

    // Staging geometry: 4 threads/row, 16 floats (4x16B) each for K and V
    const int srow = tid >> 2;
    const int scol = (tid & 3) * 16;
    const float* kg0 = Kg + (size_t)srow * HD + scol;
    const float* vg0 = Vg + (size_t)srow * HD + scol;
    const uint32_t kd0 = smem_u32(sm + srow * KS_STR + scol);
    const uint32_t vd0 = smem_u32(sm + 64 * KS_STR + srow * VS_STR + scol);

    // Q fragments: register-resident all kernel (g_q normal layout)
    unsigned qf[8][4];
    {
        const float* Q0 = Qg + (size_t)(q0 + wrow + g) * HD;
        const float* Q1 = Q0 + 8 * HD;
#pragma unroll
        for (int ks = 0; ks < 8; ks++) {
            qf[ks][0] = __float_as_uint(Q0[ks * 8 + t]);
            qf[ks][1] = __float_as_uint(Q1[ks * 8 + t]);
            qf[ks][2] = __float_as_uint(Q0[ks * 8 + t + 4]);
            qf[ks][3] = __float_as_uint(Q1[ks * 8 + t + 4]);
        }
    }

    // Prologue: stage tiles 0 and 1
#pragma unroll
    for (int it = 0; it < 2; it++) {
        const uint32_t soff = it * STAGE_W * 4;
        const size_t goff = (size_t)it * 64 * HD;
#pragma unroll
        for (int i = 0; i < 4; i++) {
            cp_async16(kd0 + soff + i * 16, kg0 + goff + i * 4);
            cp_async16(vd0 + soff + i * 16, vg0 + goff + i * 4);
        }
        cp_commit();
    }

    float o[8][4];
#pragma unroll
    for (int nj = 0; nj < 8; nj++)
#pragma unroll
        for (int e = 0; e < 4; e++) o[nj][e] = 0.f;
    float m0 = NEGF, m1 = NEGF, l0 = 0.f, l1 = 0.f;

    const unsigned* adj0 = g_adj + (q0 + wrow + g) * 32;
    const unsigned* adj1 = adj0 + 8 * 32;
    const int srcLo = (lane & ~3) | (t >> 1);
    const int srcHi = srcLo + 2;
    const bool oddT = (t & 1);

#pragma unroll 1
    for (int it = 0; it < 16; it++) {
        const int buf = it & 1;
        const int k0 = it * 64;
        if (it < 15) cp_wait<1>(); else cp_wait<0>();
        __syncthreads();

        const float* Ks = sm + buf * STAGE_W;
        const float* Vs = Ks + 64 * KS_STR;

        // S = Q K^T  (K cols d-interleaved: one LDS.64 per fragment pair)
        float sa[8][4];
#pragma unroll
        for (int ni = 0; ni < 8; ni++)
#pragma unroll
            for (int e = 0; e < 4; e++) sa[ni][e] = 0.f;
#pragma unroll
        for (int ks = 0; ks < 8; ks++) {
            const int kb2 = ks * 8 + 2 * t;
#pragma unroll
            for (int ni = 0; ni < 8; ni++) {
                uint2 kk = *(const uint2*)(Ks + (ni * 8 + g) * KS_STR + kb2);
                mma_tf32(sa[ni], qf[ks], kk.x, kk.y);
            }
        }

        // Mask + tile row-max
        uint2 w0 = *(const uint2*)(adj0 + (k0 >> 5));
        uint2 w1 = *(const uint2*)(adj1 + (k0 >> 5));
        unsigned long long M0 = ((unsigned long long)w0.y << 32) | w0.x;
        unsigned long long M1 = ((unsigned long long)w1.y << 32) | w1.x;

        float tm0 = NEGF, tm1 = NEGF;
#pragma unroll
        for (int ni = 0; ni < 8; ni++) {
            const int c = ni * 8 + 2 * t;
            sa[ni][0] = ((M0 >> c) & 1ULL) ? NEGF : sa[ni][0];
            sa[ni][1] = ((M0 >> (c + 1)) & 1ULL) ? NEGF : sa[ni][1];
            sa[ni][2] = ((M1 >> c) & 1ULL) ? NEGF : sa[ni][2];
            sa[ni][3] = ((M1 >> (c + 1)) & 1ULL) ? NEGF : sa[ni][3];
            tm0 = fmaxf(tm0, fmaxf(sa[ni][0], sa[ni][1]));
            tm1 = fmaxf(tm1, fmaxf(sa[ni][2], sa[ni][3]));
        }
        tm0 = fmaxf(tm0, __shfl_xor_sync(0xffffffffu, tm0, 1));
        tm0 = fmaxf(tm0, __shfl_xor_sync(0xffffffffu, tm0, 2));
        tm1 = fmaxf(tm1, __shfl_xor_sync(0xffffffffu, tm1, 1));
        tm1 = fmaxf(tm1, __shfl_xor_sync(0xffffffffu, tm1, 2));

        const float mn0 = fmaxf(m0, tm0);
        const float mn1 = fmaxf(m1, tm1);
        const float sc0 = __expf(m0 - mn0);
        const float sc1 = __expf(m1 - mn1);
        m0 = mn0; m1 = mn1;

#pragma unroll
        for (int nj = 0; nj < 8; nj++) {
            o[nj][0] *= sc0; o[nj][1] *= sc0;
            o[nj][2] *= sc1; o[nj][3] *= sc1;
        }

        // Fused softmax + PV via register permute
        float rs0 = 0.f, rs1 = 0.f;
#pragma unroll
        for (int ni = 0; ni < 8; ni++) {
            float p00 = __expf(sa[ni][0] - mn0);
            float p01 = __expf(sa[ni][1] - mn0);
            float p10 = __expf(sa[ni][2] - mn1);
            float p11 = __expf(sa[ni][3] - mn1);
            rs0 += p00 + p01;
            rs1 += p10 + p11;

            unsigned u0 = f2tf32(p00), u1 = f2tf32(p01);
            unsigned u2 = f2tf32(p10), u3 = f2tf32(p11);

            unsigned af[4];
            unsigned x0 = __shfl_sync(0xffffffffu, u0, srcLo);
            unsigned x1 = __shfl_sync(0xffffffffu, u1, srcLo);
            af[0] = oddT ? x1 : x0;
            unsigned y0 = __shfl_sync(0xffffffffu, u2, srcLo);
            unsigned y1 = __shfl_sync(0xffffffffu, u3, srcLo);
            af[1] = oddT ? y1 : y0;
            unsigned z0 = __shfl_sync(0xffffffffu, u0, srcHi);
            unsigned z1 = __shfl_sync(0xffffffffu, u1, srcHi);
            af[2] = oddT ? z1 : z0;
            unsigned w2 = __shfl_sync(0xffffffffu, u2, srcHi);
            unsigned w3 = __shfl_sync(0xffffffffu, u3, srcHi);
            af[3] = oddT ? w3 : w2;

            const unsigned* V0 = (const unsigned*)(Vs + (ni * 8 + t) * VS_STR);
            const unsigned* V1 = (const unsigned*)(Vs + (ni * 8 + t + 4) * VS_STR);
#pragma unroll
            for (int nj = 0; nj < 8; nj++)
                mma_tf32(o[nj], af, V0[nj * 8 + g], V1[nj * 8 + g]);
        }
        rs0 += __shfl_xor_sync(0xffffffffu, rs0, 1);
        rs0 += __shfl_xor_sync(0xffffffffu, rs0, 2);
        rs1 += __shfl_xor_sync(0xffffffffu, rs1, 1);
        rs1 += __shfl_xor_sync(0xffffffffu, rs1, 2);
        l0 = l0 * sc0 + rs0;
        l1 = l1 * sc1 + rs1;

        __syncthreads();   // compute on buf done -> safe to restage buf
        if (it + 2 < 16) {
            const uint32_t soff = buf * STAGE_W * 4;
            const size_t goff = (size_t)(it + 2) * 64 * HD;
#pragma unroll
            for (int i = 0; i < 4; i++) {
                cp_async16(kd0 + soff + i * 16, kg0 + goff + i * 4);
                cp_async16(vd0 + soff + i * 16, vg0 + goff + i * 4);
            }
            cp_commit();
        }
    }

    // Epilogue: normalize, tf32-round, write g_attn d-interleaved
    const float il0 = 1.f / l0;
    const float il1 = 1.f / l1;
    const int b = bh >> 4;
    const int h = bh & 15;
    const int qr0 = q0 + wrow + g;
    const int p0 = il8(2 * t);
    const int p1 = il8(2 * t + 1);
    float* out0 = g_attn + ((size_t)b * LL + qr0) * DD + h * HD;
    float* out1 = g_attn + ((size_t)b * LL + qr0 + 8) * DD + h * HD;
#pragma unroll
    for (int nj = 0; nj < 8; nj++) {
        const int cb = nj * 8;
        out0[cb + p0] = __uint_as_float(f2tf32(o[nj][0] * il0));
        out0[cb + p1] = __uint_as_float(f2tf32(o[nj][1] * il0));
        out1[cb + p0] = __uint_as_float(f2tf32(o[nj][2] * il1));
        out1[cb + p1] = __uint_as_float(f2tf32(o[nj][3] * il1));
    }
}

// ---------------------------------------------------------------------------
// Launch
// ---------------------------------------------------------------------------
extern "C" void kernel_launch(void* const* d_in, const int* in_sizes, int n_in,
                              void* d_out, int out_size) {
    const float* x     = (const float*)d_in[0];   // [B,L,D]
    const int*   edges = (const int*)d_in[1];     // [E,2]
    const float* w_qkv = (const float*)d_in[2];   // [3D,D]
    const float* b_qkv = (const float*)d_in[3];   // [3D]
    const float* w_out = (const float*)d_in[4];   // [D,D]
    const float* b_out = (const float*)d_in[5];   // [D]
    float* out = (float*)d_out;                   // [B,L,D]

    // >48KB dynamic smem (host attrs, capture-safe)
    cudaFuncSetAttribute(attn_mma_k, cudaFuncAttributeMaxDynamicSharedMemorySize,
                         ATTN_SMEM);
    cudaFuncSetAttribute(gemm_k<1>, cudaFuncAttributeMaxDynamicSharedMemorySize,
                         GEMM_SMEM);
    cudaFuncSetAttribute(gemm_k<0>, cudaFuncAttributeMaxDynamicSharedMemorySize,
                         GEMM_SMEM);

    float* xc; cudaGetSymbolAddress((void**)&xc, g_xc);
    float* wq; cudaGetSymbolAddress((void**)&wq, g_wq);
    float* wo; cudaGetSymbolAddress((void**)&wo, g_wo);

    // 1) adjacency + operand conversion (tf32 + k-interleave)
    adj_clear_k<<<(LL * 32 + 255) / 256, 256>>>();
    adj_scatter_k<<<(EE + 255) / 256, 256>>>(edges);
    conv_tf32_il_k<<<(BB * LL * DD / 8 + 255) / 256, 256>>>(x, xc, BB * LL * DD / 8);
    conv_tf32_il_k<<<(D3 * DD / 8 + 255) / 256, 256>>>(w_qkv, wq, D3 * DD / 8);
    conv_tf32_il_k<<<(DD * DD / 8 + 255) / 256, 256>>>(w_out, wo, DD * DD / 8);

    // 2) fused QKV projection (+bias, +q scaling, +head scatter) [tf32 TC]
    {
        dim3 grid(D3 / 128, (BB * LL) / 128);   // 24 x 32
        gemm_k<1><<<grid, 256, GEMM_SMEM>>>(b_qkv, nullptr);
    }

    // 3) masked flash attention [tf32 TC, cp.async pipeline, 2 blocks/SM]
    {
        dim3 grid(LL / 128, BB * HH);           // 8 x 64
        attn_mma_k<<<grid, 256, ATTN_SMEM>>>();
    }

    // 4) output projection (+bias) -> d_out [tf32 TC]
    {
        dim3 grid(DD / 128, (BB * LL) / 128);   // 8 x 32
        gemm_k<0><<<grid, 256, GEMM_SMEM>>>(b_out, out);
    }
}

// round 11
// speedup vs baseline: 1.5322x; 1.5322x over previous
#include <cuda_runtime.h>
#include <cuda_fp16.h>
#include <math.h>
#include <stdint.h>

// Problem constants
#define BB 4
#define LL 1024
#define DD 1024
#define HH 16
#define HD 64
#define EE 16384
#define D3 3072

#define NEGF (-1e30f)

// ---------------------------------------------------------------------------
// Scratch (static device globals; no allocation allowed)
// ---------------------------------------------------------------------------
__device__ __half g_q[(size_t)BB * HH * LL * HD];   // [B,H,L,HD] fp16, q*0.125
__device__ __half g_k[(size_t)BB * HH * LL * HD];   // [B,H,L,HD] fp16
__device__ __half g_v[(size_t)BB * HH * LL * HD];   // [B,H, L/2 kp, 64 d, 2] key-pair interleaved
__device__ __half g_attn[(size_t)BB * LL * DD];     // [B,L,D] fp16
__device__ unsigned g_adj[LL * (LL / 32)];          // bitmask

// ---------------------------------------------------------------------------
// Helpers
// ---------------------------------------------------------------------------
__device__ __forceinline__ unsigned pack_h2(float lo, float hi) {
    unsigned u;
    asm("cvt.rn.f16x2.f32 %0, %1, %2;" : "=r"(u) : "f"(hi), "f"(lo));
    return u;
}

__device__ __forceinline__ void mma_f16(float* d, const unsigned* a,
                                        unsigned b0, unsigned b1) {
    asm volatile(
        "mma.sync.aligned.m16n8k16.row.col.f32.f16.f16.f32 "
        "{%0,%1,%2,%3}, {%4,%5,%6,%7}, {%8,%9}, {%0,%1,%2,%3};"
        : "+f"(d[0]), "+f"(d[1]), "+f"(d[2]), "+f"(d[3])
        : "r"(a[0]), "r"(a[1]), "r"(a[2]), "r"(a[3]), "r"(b0), "r"(b1));
}

__device__ __forceinline__ uint32_t smem_u32(const void* p) {
    uint32_t a;
    asm("{ .reg .u64 t; cvta.to.shared.u64 t, %1; cvt.u32.u64 %0, t; }"
        : "=r"(a) : "l"(p));
    return a;
}

__device__ __forceinline__ void cp_async16(uint32_t saddr, const void* gptr) {
    asm volatile("cp.async.cg.shared.global [%0], [%1], 16;"
                 :: "r"(saddr), "l"(gptr) : "memory");
}
__device__ __forceinline__ void cp_commit() {
    asm volatile("cp.async.commit_group;" ::: "memory");
}
template <int N>
__device__ __forceinline__ void cp_wait() {
    asm volatile("cp.async.wait_group %0;" :: "n"(N) : "memory");
}

// ---------------------------------------------------------------------------
// Kernel 1: adjacency
// ---------------------------------------------------------------------------
__global__ void adj_clear_k() {
    int i = blockIdx.x * blockDim.x + threadIdx.x;
    if (i < LL * (LL / 32)) g_adj[i] = 0u;
}

__global__ void adj_scatter_k(const int* __restrict__ edges) {
    int e = blockIdx.x * blockDim.x + threadIdx.x;
    if (e >= EE) return;
    int a = edges[2 * e + 0];
    int b = edges[2 * e + 1];
    atomicOr(&g_adj[a * 32 + (b >> 5)], 1u << (b & 31));
    atomicOr(&g_adj[b * 32 + (a >> 5)], 1u << (a & 31));
}

// ---------------------------------------------------------------------------
// FP16 tensor-core GEMM (m16n8k16): C[m,n] = sum_k A[m,k]*B[n,k] + bias[n]
// BM=BN=128, BK=32, 8 warps, warp tile 64x32; fp32 accumulate.
// Smem: half, row stride 40 halves (20 words): frag banks {20g+t} conflict-free.
// MODE 1: A=x(f32), B=w_qkv(f32) -> Q/K/V fp16 (V key-pair interleaved), q*0.125
// MODE 0: A=g_attn(f16), B=w_out(f32) -> Cout f32 row-major (+bias)
// ---------------------------------------------------------------------------
#define GSTR 40                       // halves per smem row

template <int MODE>
__global__ void __launch_bounds__(256, 2) gemm_k(const float* __restrict__ Af,
                                                 const float* __restrict__ Bf,
                                                 const float* __restrict__ bias,
                                                 float* __restrict__ Cout) {
    constexpr int K = 1024;
    __shared__ __half smh[2 * 128 * GSTR];    // A tile | B tile
    __half* AsH = smh;
    __half* BsH = smh + 128 * GSTR;

    const int tid = threadIdx.x;
    const int m0 = blockIdx.y * 128;
    const int n0 = blockIdx.x * 128;

    const int lrow = tid >> 1;
    const int lk   = (tid & 1) * 16;          // k offset (elements)
    const float*  AgF = Af + (size_t)(m0 + lrow) * K + lk;
    const __half* AgH = g_attn + (size_t)(m0 + lrow) * K + lk;
    const float*  Bg  = Bf + (size_t)(n0 + lrow) * K + lk;

    const int wid  = tid >> 5;
    const int lane = tid & 31;
    const int wm   = (wid & 1) * 64;
    const int wn   = (wid >> 1) * 32;
    const int g    = lane >> 2;
    const int t    = lane & 3;

    float acc[4][4][4];
#pragma unroll
    for (int mi = 0; mi < 4; mi++)
#pragma unroll
        for (int ni = 0; ni < 4; ni++)
#pragma unroll
            for (int e = 0; e < 4; e++) acc[mi][ni][e] = 0.f;

    // Prefetch first k-tile
    float4 paf[4]; uint4 pah0, pah1; float4 pbf[4];
    if (MODE == 1) {
#pragma unroll
        for (int j = 0; j < 4; j++) paf[j] = *(const float4*)(AgF + 4 * j);
    } else {
        pah0 = *(const uint4*)(AgH);
        pah1 = *(const uint4*)(AgH + 8);
    }
#pragma unroll
    for (int j = 0; j < 4; j++) pbf[j] = *(const float4*)(Bg + 4 * j);

    for (int k0 = 0; k0 < K; k0 += 32) {
        __syncthreads();
        __half* Ad = AsH + lrow * GSTR + lk;
        __half* Bd = BsH + lrow * GSTR + lk;
        if (MODE == 1) {
            *(uint4*)Ad = make_uint4(pack_h2(paf[0].x, paf[0].y), pack_h2(paf[0].z, paf[0].w),
                                     pack_h2(paf[1].x, paf[1].y), pack_h2(paf[1].z, paf[1].w));
            *(uint4*)(Ad + 8) = make_uint4(pack_h2(paf[2].x, paf[2].y), pack_h2(paf[2].z, paf[2].w),
                                           pack_h2(paf[3].x, paf[3].y), pack_h2(paf[3].z, paf[3].w));
        } else {
            *(uint4*)Ad = pah0;
            *(uint4*)(Ad + 8) = pah1;
        }
        *(uint4*)Bd = make_uint4(pack_h2(pbf[0].x, pbf[0].y), pack_h2(pbf[0].z, pbf[0].w),
                                 pack_h2(pbf[1].x, pbf[1].y), pack_h2(pbf[1].z, pbf[1].w));
        *(uint4*)(Bd + 8) = make_uint4(pack_h2(pbf[2].x, pbf[2].y), pack_h2(pbf[2].z, pbf[2].w),
                                       pack_h2(pbf[3].x, pbf[3].y), pack_h2(pbf[3].z, pbf[3].w));
        __syncthreads();

        if (k0 + 32 < K) {
            if (MODE == 1) {
#pragma unroll
                for (int j = 0; j < 4; j++)
                    paf[j] = *(const float4*)(AgF + k0 + 32 + 4 * j);
            } else {
                pah0 = *(const uint4*)(AgH + k0 + 32);
                pah1 = *(const uint4*)(AgH + k0 + 40);
            }
#pragma unroll
            for (int j = 0; j < 4; j++)
                pbf[j] = *(const float4*)(Bg + k0 + 32 + 4 * j);
        }

        const unsigned* Aw = (const unsigned*)AsH;
        const unsigned* Bw = (const unsigned*)BsH;
#pragma unroll
        for (int ks = 0; ks < 2; ks++) {
            const int kw = ks * 8;            // word offset within row (16 words/row)
            unsigned af[4][4];
#pragma unroll
            for (int mi = 0; mi < 4; mi++) {
                const int r = wm + mi * 16 + g;
                const int base = r * 20 + kw; // 20 words per row
                af[mi][0] = Aw[base + t];
                af[mi][1] = Aw[base + 160 + t];        // +8 rows
                af[mi][2] = Aw[base + t + 4];
                af[mi][3] = Aw[base + 160 + t + 4];
            }
            unsigned b0[4], b1[4];
#pragma unroll
            for (int ni = 0; ni < 4; ni++) {
                const int c = wn + ni * 8 + g;
                b0[ni] = Bw[c * 20 + kw + t];
                b1[ni] = Bw[c * 20 + kw + t + 4];
            }
#pragma unroll
            for (int mi = 0; mi < 4; mi++)
#pragma unroll
                for (int ni = 0; ni < 4; ni++)
                    mma_f16(acc[mi][ni], af[mi], b0[ni], b1[ni]);
        }
    }

    const int g2t = 2 * t;
    if (MODE == 1) {
        const int part = n0 >> 10;     // 128-tile never crosses a 1024 boundary
        const float qs = (part == 0) ? 0.125f : 1.0f;
#pragma unroll
        for (int mi = 0; mi < 4; mi++) {
#pragma unroll
            for (int hf = 0; hf < 2; hf++) {
                const int m  = m0 + wm + mi * 16 + g + hf * 8;
                const int bb = m >> 10;
                const int ll = m & 1023;
#pragma unroll
                for (int ni = 0; ni < 4; ni++) {
                    const int col = n0 + wn + ni * 8 + g2t;
                    const int nn  = col & 1023;
                    const int h   = nn >> 6;
                    const int d   = nn & 63;
                    float v0 = (acc[mi][ni][hf * 2 + 0] + bias[col]) * qs;
                    float v1 = (acc[mi][ni][hf * 2 + 1] + bias[col + 1]) * qs;
                    if (part == 2) {
                        // V: key-pair interleaved [kp][d][2]
                        __half* vb = g_v + (((size_t)bb * HH + h) * (LL / 2) + (ll >> 1)) * 128 + (ll & 1);
                        vb[2 * d]       = __float2half_rn(v0);
                        vb[2 * (d + 1)] = __float2half_rn(v1);
                    } else {
                        __half* db = ((part == 0) ? g_q : g_k) +
                                     (((size_t)bb * HH + h) * LL + ll) * HD + d;
                        *(unsigned*)db = pack_h2(v0, v1);
                    }
                }
            }
        }
    } else {
#pragma unroll
        for (int mi = 0; mi < 4; mi++) {
#pragma unroll
            for (int hf = 0; hf < 2; hf++) {
                const int m = m0 + wm + mi * 16 + g + hf * 8;
#pragma unroll
                for (int ni = 0; ni < 4; ni++) {
                    const int col = n0 + wn + ni * 8 + g2t;
                    float* p = Cout + (size_t)m * DD + col;
                    p[0] = acc[mi][ni][hf * 2 + 0] + bias[col];
                    p[1] = acc[mi][ni][hf * 2 + 1] + bias[col + 1];
                }
            }
        }
    }
}

// ---------------------------------------------------------------------------
// Kernel 3: fp16 tensor-core masked flash attention, v5.
// m16n8k16: half the mmas, zero shuffles (C-frag pairs == PV A-frag half2s).
// K smem: 64 rows x 144B (stride 36 words, banks {4g+t}); V smem (key-pair
// interleaved): 32 rows x 288B (stride 72 words, banks {8t+g}).
// cp.async double-buffered. Block 256 thr / 8 warps, 128 q x one (b,h).
// ---------------------------------------------------------------------------
#define KSB 9216                       // K tile bytes (64*144)
#define VSB 9216                       // V tile bytes (32*288)
#define STAGEB (KSB + VSB)             // 18432
// total static smem: 2*STAGEB = 36864 B

__global__ void __launch_bounds__(256, 2) attn_mma_k() {
    __shared__ char sm[2 * STAGEB];

    const int bh   = blockIdx.y;
    const int tid  = threadIdx.x;
    const int wid  = tid >> 5;
    const int lane = tid & 31;
    const int g    = lane >> 2;
    const int t    = lane & 3;
    const int q0   = blockIdx.x * 128;
    const int wrow = wid * 16;

    const __half* Qg = g_q + (size_t)bh * LL * HD;
    const __half* Kg = g_k + (size_t)bh * LL * HD;
    const __half* Vg = g_v + (size_t)bh * (LL / 2) * 128;

    // Staging geometry
    const int krow = tid >> 2;                 // 0..63
    const int kcol = (tid & 3) * 16;           // halves
    const __half* kg0 = Kg + (size_t)krow * HD + kcol;
    const uint32_t kd0 = smem_u32(sm) + krow * 144 + (tid & 3) * 32;
    const int vrow = tid >> 3;                 // 0..31 (kp rows)
    const int vcol = (tid & 7) * 16;           // halves
    const __half* vg0 = Vg + (size_t)vrow * 128 + vcol;
    const uint32_t vd0 = smem_u32(sm) + KSB + vrow * 288 + (tid & 7) * 32;

    // Q fragments (register-resident): qf[ks][.] covers hd 16*ks..16*ks+15
    unsigned qf[4][4];
    {
        const unsigned* Q0w = (const unsigned*)(Qg + (size_t)(q0 + wrow + g) * HD);
        const unsigned* Q1w = Q0w + 8 * (HD / 2);
#pragma unroll
        for (int ks = 0; ks < 4; ks++) {
            qf[ks][0] = Q0w[ks * 8 + t];
            qf[ks][1] = Q1w[ks * 8 + t];
            qf[ks][2] = Q0w[ks * 8 + t + 4];
            qf[ks][3] = Q1w[ks * 8 + t + 4];
        }
    }

    // Prologue: stage tiles 0 and 1
#pragma unroll
    for (int it = 0; it < 2; it++) {
        const uint32_t soff = it * STAGEB;
        const size_t kgo = (size_t)it * 64 * HD;
        const size_t vgo = (size_t)it * 32 * 128;
        cp_async16(kd0 + soff, kg0 + kgo);
        cp_async16(kd0 + soff + 16, kg0 + kgo + 8);
        cp_async16(vd0 + soff, vg0 + vgo);
        cp_async16(vd0 + soff + 16, vg0 + vgo + 8);
        cp_commit();
    }

    float o[8][4];
#pragma unroll
    for (int nj = 0; nj < 8; nj++)
#pragma unroll
        for (int e = 0; e < 4; e++) o[nj][e] = 0.f;
    float m0 = NEGF, m1 = NEGF, l0 = 0.f, l1 = 0.f;

    const unsigned* adj0 = g_adj + (q0 + wrow + g) * 32;
    const unsigned* adj1 = adj0 + 8 * 32;

#pragma unroll 1
    for (int it = 0; it < 16; it++) {
        const int buf = it & 1;
        const int k0 = it * 64;
        if (it < 15) cp_wait<1>(); else cp_wait<0>();
        __syncthreads();

        const unsigned* Kw = (const unsigned*)(sm + buf * STAGEB);
        const unsigned* Vw = (const unsigned*)(sm + buf * STAGEB + KSB);

        // S = Q K^T : 4 hd-chunks x 8 key-blocks
        float sa[8][4];
#pragma unroll
        for (int ni = 0; ni < 8; ni++)
#pragma unroll
            for (int e = 0; e < 4; e++) sa[ni][e] = 0.f;
#pragma unroll
        for (int ks = 0; ks < 4; ks++) {
#pragma unroll
            for (int ni = 0; ni < 8; ni++) {
                const int base = (ni * 8 + g) * 36 + ks * 8;  // 36 words/row
                mma_f16(sa[ni], qf[ks], Kw[base + t], Kw[base + t + 4]);
            }
        }

        // Mask + tile row-max
        uint2 w0 = *(const uint2*)(adj0 + (k0 >> 5));
        uint2 w1 = *(const uint2*)(adj1 + (k0 >> 5));
        unsigned long long M0 = ((unsigned long long)w0.y << 32) | w0.x;
        unsigned long long M1 = ((unsigned long long)w1.y << 32) | w1.x;

        float tm0 = NEGF, tm1 = NEGF;
#pragma unroll
        for (int ni = 0; ni < 8; ni++) {
            const int c = ni * 8 + 2 * t;
            sa[ni][0] = ((M0 >> c) & 1ULL) ? NEGF : sa[ni][0];
            sa[ni][1] = ((M0 >> (c + 1)) & 1ULL) ? NEGF : sa[ni][1];
            sa[ni][2] = ((M1 >> c) & 1ULL) ? NEGF : sa[ni][2];
            sa[ni][3] = ((M1 >> (c + 1)) & 1ULL) ? NEGF : sa[ni][3];
            tm0 = fmaxf(tm0, fmaxf(sa[ni][0], sa[ni][1]));
            tm1 = fmaxf(tm1, fmaxf(sa[ni][2], sa[ni][3]));
        }
        tm0 = fmaxf(tm0, __shfl_xor_sync(0xffffffffu, tm0, 1));
        tm0 = fmaxf(tm0, __shfl_xor_sync(0xffffffffu, tm0, 2));
        tm1 = fmaxf(tm1, __shfl_xor_sync(0xffffffffu, tm1, 1));
        tm1 = fmaxf(tm1, __shfl_xor_sync(0xffffffffu, tm1, 2));

        const float mn0 = fmaxf(m0, tm0);
        const float mn1 = fmaxf(m1, tm1);
        const float sc0 = __expf(m0 - mn0);
        const float sc1 = __expf(m1 - mn1);
        m0 = mn0; m1 = mn1;

#pragma unroll
        for (int nj = 0; nj < 8; nj++) {
            o[nj][0] *= sc0; o[nj][1] *= sc0;
            o[nj][2] *= sc1; o[nj][3] *= sc1;
        }

        // Fused softmax + PV: per 16-key block, C-frag pairs pack straight
        // into the PV A-fragment (no shuffles).
        float rs0 = 0.f, rs1 = 0.f;
#pragma unroll
        for (int kb = 0; kb < 4; kb++) {
            const int nA = 2 * kb, nB = 2 * kb + 1;
            float pA0 = __expf(sa[nA][0] - mn0);
            float pA1 = __expf(sa[nA][1] - mn0);
            float pA2 = __expf(sa[nA][2] - mn1);
            float pA3 = __expf(sa[nA][3] - mn1);
            float pB0 = __expf(sa[nB][0] - mn0);
            float pB1 = __expf(sa[nB][1] - mn0);
            float pB2 = __expf(sa[nB][2] - mn1);
            float pB3 = __expf(sa[nB][3] - mn1);
            rs0 += pA0 + pA1 + pB0 + pB1;
            rs1 += pA2 + pA3 + pB2 + pB3;

            unsigned af[4];
            af[0] = pack_h2(pA0, pA1);   // row g,   keys 2t,2t+1
            af[1] = pack_h2(pA2, pA3);   // row g+8, keys 2t,2t+1
            af[2] = pack_h2(pB0, pB1);   // row g,   keys 2t+8,2t+9
            af[3] = pack_h2(pB2, pB3);   // row g+8, keys 2t+8,2t+9

            const unsigned* V0 = Vw + (kb * 8 + t) * 72;        // 72 words/row
            const unsigned* V1 = Vw + (kb * 8 + t + 4) * 72;
#pragma unroll
            for (int nj = 0; nj < 8; nj++)
                mma_f16(o[nj], af, V0[nj * 8 + g], V1[nj * 8 + g]);
        }
        rs0 += __shfl_xor_sync(0xffffffffu, rs0, 1);
        rs0 += __shfl_xor_sync(0xffffffffu, rs0, 2);
        rs1 += __shfl_xor_sync(0xffffffffu, rs1, 1);
        rs1 += __shfl_xor_sync(0xffffffffu, rs1, 2);
        l0 = l0 * sc0 + rs0;
        l1 = l1 * sc1 + rs1;

        __syncthreads();   // compute on buf done -> safe to restage
        if (it + 2 < 16) {
            const uint32_t soff = buf * STAGEB;
            const size_t kgo = (size_t)(it + 2) * 64 * HD;
            const size_t vgo = (size_t)(it + 2) * 32 * 128;
            cp_async16(kd0 + soff, kg0 + kgo);
            cp_async16(kd0 + soff + 16, kg0 + kgo + 8);
            cp_async16(vd0 + soff, vg0 + vgo);
            cp_async16(vd0 + soff + 16, vg0 + vgo + 8);
            cp_commit();
        }
    }

    // Epilogue: normalize, write g_attn fp16 [B,L,D]
    const float il0 = 1.f / l0;
    const float il1 = 1.f / l1;
    const int b = bh >> 4;
    const int h = bh & 15;
    const int qr0 = q0 + wrow + g;
    __half* out0 = g_attn + ((size_t)b * LL + qr0) * DD + h * HD;
    __half* out1 = g_attn + ((size_t)b * LL + qr0 + 8) * DD + h * HD;
#pragma unroll
    for (int nj = 0; nj < 8; nj++) {
        const int c = nj * 8 + 2 * t;
        *(unsigned*)(out0 + c) = pack_h2(o[nj][0] * il0, o[nj][1] * il0);
        *(unsigned*)(out1 + c) = pack_h2(o[nj][2] * il1, o[nj][3] * il1);
    }
}

// ---------------------------------------------------------------------------
// Launch
// ---------------------------------------------------------------------------
extern "C" void kernel_launch(void* const* d_in, const int* in_sizes, int n_in,
                              void* d_out, int out_size) {
    const float* x     = (const float*)d_in[0];   // [B,L,D]
    const int*   edges = (const int*)d_in[1];     // [E,2]
    const float* w_qkv = (const float*)d_in[2];   // [3D,D]
    const float* b_qkv = (const float*)d_in[3];   // [3D]
    const float* w_out = (const float*)d_in[4];   // [D,D]
    const float* b_out = (const float*)d_in[5];   // [D]
    float* out = (float*)d_out;                   // [B,L,D]

    // 1) adjacency bitmask
    adj_clear_k<<<(LL * 32 + 255) / 256, 256>>>();
    adj_scatter_k<<<(EE + 255) / 256, 256>>>(edges);

    // 2) fused QKV projection (+bias, +q scaling, +head scatter) [fp16 TC]
    {
        dim3 grid(D3 / 128, (BB * LL) / 128);   // 24 x 32
        gemm_k<1><<<grid, 256>>>(x, w_qkv, b_qkv, nullptr);
    }

    // 3) masked flash attention [fp16 TC, cp.async pipeline, 2 blocks/SM]
    {
        dim3 grid(LL / 128, BB * HH);           // 8 x 64
        attn_mma_k<<<grid, 256>>>();
    }

    // 4) output projection (+bias) -> d_out [fp16 TC]
    {
        dim3 grid(DD / 128, (BB * LL) / 128);   // 8 x 32
        gemm_k<0><<<grid, 256>>>(nullptr, w_out, b_out, out);
    }
}

// round 12
// speedup vs baseline: 2.0063x; 1.3095x over previous
#include <cuda_runtime.h>
#include <cuda_fp16.h>
#include <math.h>
#include <stdint.h>

// Problem constants
#define BB 4
#define LL 1024
#define DD 1024
#define HH 16
#define HD 64
#define EE 16384
#define D3 3072

#define NEGF (-1e30f)

// ---------------------------------------------------------------------------
// Scratch (static device globals; no allocation allowed)
// ---------------------------------------------------------------------------
__device__ __half g_q[(size_t)BB * HH * LL * HD];   // [B,H,L,HD] fp16, q*0.125
__device__ __half g_k[(size_t)BB * HH * LL * HD];   // [B,H,L,HD] fp16
__device__ __half g_v[(size_t)BB * HH * LL * HD];   // [B,H,L/2,64,2] key-pair interleaved
__device__ __half g_attn[(size_t)BB * LL * DD];     // [B,L,D] fp16
__device__ unsigned g_adj[LL * (LL / 32)];          // bitmask

// fp16 copies of f32 GEMM operands (converted once per launch)
__device__ __half g_xh[(size_t)BB * LL * DD];       // x     [4096,1024]
__device__ __half g_wqh[(size_t)D3 * DD];           // w_qkv [3072,1024]
__device__ __half g_woh[(size_t)DD * DD];           // w_out [1024,1024]

// ---------------------------------------------------------------------------
// Helpers
// ---------------------------------------------------------------------------
__device__ __forceinline__ unsigned pack_h2(float lo, float hi) {
    unsigned u;
    asm("cvt.rn.f16x2.f32 %0, %1, %2;" : "=r"(u) : "f"(hi), "f"(lo));
    return u;
}

__device__ __forceinline__ void mma_f16(float* d, const unsigned* a,
                                        unsigned b0, unsigned b1) {
    asm volatile(
        "mma.sync.aligned.m16n8k16.row.col.f32.f16.f16.f32 "
        "{%0,%1,%2,%3}, {%4,%5,%6,%7}, {%8,%9}, {%0,%1,%2,%3};"
        : "+f"(d[0]), "+f"(d[1]), "+f"(d[2]), "+f"(d[3])
        : "r"(a[0]), "r"(a[1]), "r"(a[2]), "r"(a[3]), "r"(b0), "r"(b1));
}

__device__ __forceinline__ uint32_t smem_u32(const void* p) {
    uint32_t a;
    asm("{ .reg .u64 t; cvta.to.shared.u64 t, %1; cvt.u32.u64 %0, t; }"
        : "=r"(a) : "l"(p));
    return a;
}

__device__ __forceinline__ void cp_async16(uint32_t saddr, const void* gptr) {
    asm volatile("cp.async.cg.shared.global [%0], [%1], 16;"
                 :: "r"(saddr), "l"(gptr) : "memory");
}
__device__ __forceinline__ void cp_commit() {
    asm volatile("cp.async.commit_group;" ::: "memory");
}
template <int N>
__device__ __forceinline__ void cp_wait() {
    asm volatile("cp.async.wait_group %0;" :: "n"(N) : "memory");
}

// ---------------------------------------------------------------------------
// Kernel 1: adjacency
// ---------------------------------------------------------------------------
__global__ void adj_clear_k() {
    int i = blockIdx.x * blockDim.x + threadIdx.x;
    if (i < LL * (LL / 32)) g_adj[i] = 0u;
}

__global__ void adj_scatter_k(const int* __restrict__ edges) {
    int e = blockIdx.x * blockDim.x + threadIdx.x;
    if (e >= EE) return;
    int a = edges[2 * e + 0];
    int b = edges[2 * e + 1];
    atomicOr(&g_adj[a * 32 + (b >> 5)], 1u << (b & 31));
    atomicOr(&g_adj[b * 32 + (a >> 5)], 1u << (a & 31));
}

// ---------------------------------------------------------------------------
// Kernel 2: f32 -> f16 conversion (8 elements/thread)
// ---------------------------------------------------------------------------
__global__ void conv_f16_k(const float* __restrict__ in,
                           __half* __restrict__ out, int n8) {
    int i = blockIdx.x * blockDim.x + threadIdx.x;
    if (i >= n8) return;
    float4 a = ((const float4*)in)[2 * i];
    float4 b = ((const float4*)in)[2 * i + 1];
    ((uint4*)out)[i] = make_uint4(pack_h2(a.x, a.y), pack_h2(a.z, a.w),
                                  pack_h2(b.x, b.y), pack_h2(b.z, b.w));
}

// ---------------------------------------------------------------------------
// FP16 tensor-core GEMM v2 (m16n8k16, all-fp16 operands, cp.async 2-stage):
// C[m,n] = sum_k A[m,k]*B[n,k] + bias[n]
// BM=BN=128, BK=32, 8 warps, warp tile 64x32; fp32 accumulate.
// Smem rows 40 halves (20 words); frag LDS banks {20g+t} conflict-free.
// MODE 1: -> Q/K/V fp16 (V key-pair interleaved), q*0.125
// MODE 0: -> Cout f32 row-major (+bias)
// ---------------------------------------------------------------------------
#define GSTR 40                           // halves per smem row
#define GMATB (128 * GSTR * 2)            // bytes per matrix per stage (10240)
#define GSTGB (2 * GMATB)                 // bytes per stage (20480)
// static smem: 2 stages = 40960 B

template <int MODE>
__global__ void __launch_bounds__(256, 2) gemm_k(const __half* __restrict__ A,
                                                 const __half* __restrict__ Bm,
                                                 const float* __restrict__ bias,
                                                 float* __restrict__ Cout) {
    constexpr int K = 1024;
    __shared__ char smc[2 * GSTGB];

    const int tid = threadIdx.x;
    const int m0 = blockIdx.y * 128;
    const int n0 = blockIdx.x * 128;

    // Staging: 2 threads/row, 16 halves (2x16B) each
    const int lrow = tid >> 1;
    const int lk   = (tid & 1) * 16;
    const __half* Ag = A  + (size_t)(m0 + lrow) * K + lk;
    const __half* Bg = Bm + (size_t)(n0 + lrow) * K + lk;
    const uint32_t sA = smem_u32(smc) + lrow * 80 + (tid & 1) * 32;

    const int wid  = tid >> 5;
    const int lane = tid & 31;
    const int wm   = (wid & 1) * 64;
    const int wn   = (wid >> 1) * 32;
    const int g    = lane >> 2;
    const int t    = lane & 3;

    float acc[4][4][4];
#pragma unroll
    for (int mi = 0; mi < 4; mi++)
#pragma unroll
        for (int ni = 0; ni < 4; ni++)
#pragma unroll
            for (int e = 0; e < 4; e++) acc[mi][ni][e] = 0.f;

    // Prologue: stage k-tiles 0,1
#pragma unroll
    for (int pt = 0; pt < 2; pt++) {
        const uint32_t base = sA + pt * GSTGB;
        cp_async16(base, Ag + pt * 32);
        cp_async16(base + 16, Ag + pt * 32 + 8);
        cp_async16(base + GMATB, Bg + pt * 32);
        cp_async16(base + GMATB + 16, Bg + pt * 32 + 8);
        cp_commit();
    }

#pragma unroll 1
    for (int it = 0; it < 32; it++) {
        const int s = it & 1;
        if (it < 31) cp_wait<1>(); else cp_wait<0>();
        __syncthreads();

        const unsigned* Aw = (const unsigned*)(smc + s * GSTGB);
        const unsigned* Bw = (const unsigned*)(smc + s * GSTGB + GMATB);

#pragma unroll
        for (int ks = 0; ks < 2; ks++) {
            const int kw = ks * 8;
            unsigned af[4][4];
#pragma unroll
            for (int mi = 0; mi < 4; mi++) {
                const int base = (wm + mi * 16 + g) * 20 + kw;
                af[mi][0] = Aw[base + t];
                af[mi][1] = Aw[base + 160 + t];
                af[mi][2] = Aw[base + t + 4];
                af[mi][3] = Aw[base + 160 + t + 4];
            }
            unsigned b0[4], b1[4];
#pragma unroll
            for (int ni = 0; ni < 4; ni++) {
                const int c = (wn + ni * 8 + g) * 20 + kw;
                b0[ni] = Bw[c + t];
                b1[ni] = Bw[c + t + 4];
            }
#pragma unroll
            for (int mi = 0; mi < 4; mi++)
#pragma unroll
                for (int ni = 0; ni < 4; ni++)
                    mma_f16(acc[mi][ni], af[mi], b0[ni], b1[ni]);
        }

        __syncthreads();
        if (it + 2 < 32) {
            const uint32_t base = sA + s * GSTGB;
            const __half* ag = Ag + (it + 2) * 32;
            const __half* bg = Bg + (it + 2) * 32;
            cp_async16(base, ag);
            cp_async16(base + 16, ag + 8);
            cp_async16(base + GMATB, bg);
            cp_async16(base + GMATB + 16, bg + 8);
            cp_commit();
        }
    }

    const int g2t = 2 * t;
    if (MODE == 1) {
        const int part = n0 >> 10;     // 128-tile never crosses a 1024 boundary
        const float qs = (part == 0) ? 0.125f : 1.0f;
#pragma unroll
        for (int mi = 0; mi < 4; mi++) {
#pragma unroll
            for (int hf = 0; hf < 2; hf++) {
                const int m  = m0 + wm + mi * 16 + g + hf * 8;
                const int bb = m >> 10;
                const int ll = m & 1023;
#pragma unroll
                for (int ni = 0; ni < 4; ni++) {
                    const int col = n0 + wn + ni * 8 + g2t;
                    const int nn  = col & 1023;
                    const int h   = nn >> 6;
                    const int d   = nn & 63;
                    float v0 = (acc[mi][ni][hf * 2 + 0] + bias[col]) * qs;
                    float v1 = (acc[mi][ni][hf * 2 + 1] + bias[col + 1]) * qs;
                    if (part == 2) {
                        // V: key-pair interleaved [kp][d][2]
                        __half* vb = g_v + (((size_t)bb * HH + h) * (LL / 2) + (ll >> 1)) * 128 + (ll & 1);
                        vb[2 * d]       = __float2half_rn(v0);
                        vb[2 * (d + 1)] = __float2half_rn(v1);
                    } else {
                        __half* db = ((part == 0) ? g_q : g_k) +
                                     (((size_t)bb * HH + h) * LL + ll) * HD + d;
                        *(unsigned*)db = pack_h2(v0, v1);
                    }
                }
            }
        }
    } else {
#pragma unroll
        for (int mi = 0; mi < 4; mi++) {
#pragma unroll
            for (int hf = 0; hf < 2; hf++) {
                const int m = m0 + wm + mi * 16 + g + hf * 8;
#pragma unroll
                for (int ni = 0; ni < 4; ni++) {
                    const int col = n0 + wn + ni * 8 + g2t;
                    float* p = Cout + (size_t)m * DD + col;
                    p[0] = acc[mi][ni][hf * 2 + 0] + bias[col];
                    p[1] = acc[mi][ni][hf * 2 + 1] + bias[col + 1];
                }
            }
        }
    }
}

// ---------------------------------------------------------------------------
// Kernel 3: fp16 tensor-core masked flash attention (unchanged from round 11).
// ---------------------------------------------------------------------------
#define KSB 9216                       // K tile bytes (64*144)
#define VSB 9216                       // V tile bytes (32*288)
#define STAGEB (KSB + VSB)             // 18432

__global__ void __launch_bounds__(256, 2) attn_mma_k() {
    __shared__ char sm[2 * STAGEB];

    const int bh   = blockIdx.y;
    const int tid  = threadIdx.x;
    const int wid  = tid >> 5;
    const int lane = tid & 31;
    const int g    = lane >> 2;
    const int t    = lane & 3;
    const int q0   = blockIdx.x * 128;
    const int wrow = wid * 16;

    const __half* Qg = g_q + (size_t)bh * LL * HD;
    const __half* Kg = g_k + (size_t)bh * LL * HD;
    const __half* Vg = g_v + (size_t)bh * (LL / 2) * 128;

    const int krow = tid >> 2;
    const __half* kg0 = Kg + (size_t)krow * HD + (tid & 3) * 16;
    const uint32_t kd0 = smem_u32(sm) + krow * 144 + (tid & 3) * 32;
    const int vrow = tid >> 3;
    const __half* vg0 = Vg + (size_t)vrow * 128 + (tid & 7) * 16;
    const uint32_t vd0 = smem_u32(sm) + KSB + vrow * 288 + (tid & 7) * 32;

    unsigned qf[4][4];
    {
        const unsigned* Q0w = (const unsigned*)(Qg + (size_t)(q0 + wrow + g) * HD);
        const unsigned* Q1w = Q0w + 8 * (HD / 2);
#pragma unroll
        for (int ks = 0; ks < 4; ks++) {
            qf[ks][0] = Q0w[ks * 8 + t];
            qf[ks][1] = Q1w[ks * 8 + t];
            qf[ks][2] = Q0w[ks * 8 + t + 4];
            qf[ks][3] = Q1w[ks * 8 + t + 4];
        }
    }

#pragma unroll
    for (int it = 0; it < 2; it++) {
        const uint32_t soff = it * STAGEB;
        const size_t kgo = (size_t)it * 64 * HD;
        const size_t vgo = (size_t)it * 32 * 128;
        cp_async16(kd0 + soff, kg0 + kgo);
        cp_async16(kd0 + soff + 16, kg0 + kgo + 8);
        cp_async16(vd0 + soff, vg0 + vgo);
        cp_async16(vd0 + soff + 16, vg0 + vgo + 8);
        cp_commit();
    }

    float o[8][4];
#pragma unroll
    for (int nj = 0; nj < 8; nj++)
#pragma unroll
        for (int e = 0; e < 4; e++) o[nj][e] = 0.f;
    float m0 = NEGF, m1 = NEGF, l0 = 0.f, l1 = 0.f;

    const unsigned* adj0 = g_adj + (q0 + wrow + g) * 32;
    const unsigned* adj1 = adj0 + 8 * 32;

#pragma unroll 1
    for (int it = 0; it < 16; it++) {
        const int buf = it & 1;
        const int k0 = it * 64;
        if (it < 15) cp_wait<1>(); else cp_wait<0>();
        __syncthreads();

        const unsigned* Kw = (const unsigned*)(sm + buf * STAGEB);
        const unsigned* Vw = (const unsigned*)(sm + buf * STAGEB + KSB);

        float sa[8][4];
#pragma unroll
        for (int ni = 0; ni < 8; ni++)
#pragma unroll
            for (int e = 0; e < 4; e++) sa[ni][e] = 0.f;
#pragma unroll
        for (int ks = 0; ks < 4; ks++) {
#pragma unroll
            for (int ni = 0; ni < 8; ni++) {
                const int base = (ni * 8 + g) * 36 + ks * 8;
                mma_f16(sa[ni], qf[ks], Kw[base + t], Kw[base + t + 4]);
            }
        }

        uint2 w0 = *(const uint2*)(adj0 + (k0 >> 5));
        uint2 w1 = *(const uint2*)(adj1 + (k0 >> 5));
        unsigned long long M0 = ((unsigned long long)w0.y << 32) | w0.x;
        unsigned long long M1 = ((unsigned long long)w1.y << 32) | w1.x;

        float tm0 = NEGF, tm1 = NEGF;
#pragma unroll
        for (int ni = 0; ni < 8; ni++) {
            const int c = ni * 8 + 2 * t;
            sa[ni][0] = ((M0 >> c) & 1ULL) ? NEGF : sa[ni][0];
            sa[ni][1] = ((M0 >> (c + 1)) & 1ULL) ? NEGF : sa[ni][1];
            sa[ni][2] = ((M1 >> c) & 1ULL) ? NEGF : sa[ni][2];
            sa[ni][3] = ((M1 >> (c + 1)) & 1ULL) ? NEGF : sa[ni][3];
            tm0 = fmaxf(tm0, fmaxf(sa[ni][0], sa[ni][1]));
            tm1 = fmaxf(tm1, fmaxf(sa[ni][2], sa[ni][3]));
        }
        tm0 = fmaxf(tm0, __shfl_xor_sync(0xffffffffu, tm0, 1));
        tm0 = fmaxf(tm0, __shfl_xor_sync(0xffffffffu, tm0, 2));
        tm1 = fmaxf(tm1, __shfl_xor_sync(0xffffffffu, tm1, 1));
        tm1 = fmaxf(tm1, __shfl_xor_sync(0xffffffffu, tm1, 2));

        const float mn0 = fmaxf(m0, tm0);
        const float mn1 = fmaxf(m1, tm1);
        const float sc0 = __expf(m0 - mn0);
        const float sc1 = __expf(m1 - mn1);
        m0 = mn0; m1 = mn1;

#pragma unroll
        for (int nj = 0; nj < 8; nj++) {
            o[nj][0] *= sc0; o[nj][1] *= sc0;
            o[nj][2] *= sc1; o[nj][3] *= sc1;
        }

        float rs0 = 0.f, rs1 = 0.f;
#pragma unroll
        for (int kb = 0; kb < 4; kb++) {
            const int nA = 2 * kb, nB = 2 * kb + 1;
            float pA0 = __expf(sa[nA][0] - mn0);
            float pA1 = __expf(sa[nA][1] - mn0);
            float pA2 = __expf(sa[nA][2] - mn1);
            float pA3 = __expf(sa[nA][3] - mn1);
            float pB0 = __expf(sa[nB][0] - mn0);
            float pB1 = __expf(sa[nB][1] - mn0);
            float pB2 = __expf(sa[nB][2] - mn1);
            float pB3 = __expf(sa[nB][3] - mn1);
            rs0 += pA0 + pA1 + pB0 + pB1;
            rs1 += pA2 + pA3 + pB2 + pB3;

            unsigned af[4];
            af[0] = pack_h2(pA0, pA1);
            af[1] = pack_h2(pA2, pA3);
            af[2] = pack_h2(pB0, pB1);
            af[3] = pack_h2(pB2, pB3);

            const unsigned* V0 = Vw + (kb * 8 + t) * 72;
            const unsigned* V1 = Vw + (kb * 8 + t + 4) * 72;
#pragma unroll
            for (int nj = 0; nj < 8; nj++)
                mma_f16(o[nj], af, V0[nj * 8 + g], V1[nj * 8 + g]);
        }
        rs0 += __shfl_xor_sync(0xffffffffu, rs0, 1);
        rs0 += __shfl_xor_sync(0xffffffffu, rs0, 2);
        rs1 += __shfl_xor_sync(0xffffffffu, rs1, 1);
        rs1 += __shfl_xor_sync(0xffffffffu, rs1, 2);
        l0 = l0 * sc0 + rs0;
        l1 = l1 * sc1 + rs1;

        __syncthreads();
        if (it + 2 < 16) {
            const uint32_t soff = buf * STAGEB;
            const size_t kgo = (size_t)(it + 2) * 64 * HD;
            const size_t vgo = (size_t)(it + 2) * 32 * 128;
            cp_async16(kd0 + soff, kg0 + kgo);
            cp_async16(kd0 + soff + 16, kg0 + kgo + 8);
            cp_async16(vd0 + soff, vg0 + vgo);
            cp_async16(vd0 + soff + 16, vg0 + vgo + 8);
            cp_commit();
        }
    }

    const float il0 = 1.f / l0;
    const float il1 = 1.f / l1;
    const int b = bh >> 4;
    const int h = bh & 15;
    const int qr0 = q0 + wrow + g;
    __half* out0 = g_attn + ((size_t)b * LL + qr0) * DD + h * HD;
    __half* out1 = g_attn + ((size_t)b * LL + qr0 + 8) * DD + h * HD;
#pragma unroll
    for (int nj = 0; nj < 8; nj++) {
        const int c = nj * 8 + 2 * t;
        *(unsigned*)(out0 + c) = pack_h2(o[nj][0] * il0, o[nj][1] * il0);
        *(unsigned*)(out1 + c) = pack_h2(o[nj][2] * il1, o[nj][3] * il1);
    }
}

// ---------------------------------------------------------------------------
// Launch
// ---------------------------------------------------------------------------
extern "C" void kernel_launch(void* const* d_in, const int* in_sizes, int n_in,
                              void* d_out, int out_size) {
    const float* x     = (const float*)d_in[0];   // [B,L,D]
    const int*   edges = (const int*)d_in[1];     // [E,2]
    const float* w_qkv = (const float*)d_in[2];   // [3D,D]
    const float* b_qkv = (const float*)d_in[3];   // [3D]
    const float* w_out = (const float*)d_in[4];   // [D,D]
    const float* b_out = (const float*)d_in[5];   // [D]
    float* out = (float*)d_out;                   // [B,L,D]

    __half* xh;  cudaGetSymbolAddress((void**)&xh, g_xh);
    __half* wqh; cudaGetSymbolAddress((void**)&wqh, g_wqh);
    __half* woh; cudaGetSymbolAddress((void**)&woh, g_woh);
    __half* ath; cudaGetSymbolAddress((void**)&ath, g_attn);

    // 1) adjacency + fp16 operand conversion
    adj_clear_k<<<(LL * 32 + 255) / 256, 256>>>();
    adj_scatter_k<<<(EE + 255) / 256, 256>>>(edges);
    conv_f16_k<<<(BB * LL * DD / 8 + 255) / 256, 256>>>(x, xh, BB * LL * DD / 8);
    conv_f16_k<<<(D3 * DD / 8 + 255) / 256, 256>>>(w_qkv, wqh, D3 * DD / 8);
    conv_f16_k<<<(DD * DD / 8 + 255) / 256, 256>>>(w_out, woh, DD * DD / 8);

    // 2) fused QKV projection (+bias, +q scaling, +head scatter) [fp16 TC]
    {
        dim3 grid(D3 / 128, (BB * LL) / 128);   // 24 x 32
        gemm_k<1><<<grid, 256>>>(xh, wqh, b_qkv, nullptr);
    }

    // 3) masked flash attention [fp16 TC, cp.async pipeline, 2 blocks/SM]
    {
        dim3 grid(LL / 128, BB * HH);           // 8 x 64
        attn_mma_k<<<grid, 256>>>();
    }

    // 4) output projection (+bias) -> d_out [fp16 TC]
    {
        dim3 grid(DD / 128, (BB * LL) / 128);   // 8 x 32
        gemm_k<0><<<grid, 256>>>(ath, woh, b_out, out);
    }
}

// round 13
// speedup vs baseline: 2.0848x; 1.0391x over previous
#include <cuda_runtime.h>
#include <cuda_fp16.h>
#include <math.h>
#include <stdint.h>

// Problem constants
#define BB 4
#define LL 1024
#define DD 1024
#define HH 16
#define HD 64
#define EE 16384
#define D3 3072

#define NEGF (-1e30f)

// ---------------------------------------------------------------------------
// Scratch (static device globals; no allocation allowed)
// ---------------------------------------------------------------------------
__device__ __half g_q[(size_t)BB * HH * LL * HD];   // [B,H,L,HD] fp16, q*0.125
__device__ __half g_k[(size_t)BB * HH * LL * HD];   // [B,H,L,HD] fp16
__device__ __half g_v[(size_t)BB * HH * LL * HD];   // [B,H,L/2,64,2] key-pair interleaved
__device__ __half g_attn[(size_t)BB * LL * DD];     // [B,L,D] fp16
__device__ unsigned g_adj[LL * (LL / 32)];          // bitmask

// fp16 copies of f32 GEMM operands (converted once per launch)
__device__ __half g_xh[(size_t)BB * LL * DD];       // x     [4096,1024]
__device__ __half g_wqh[(size_t)D3 * DD];           // w_qkv [3072,1024]
__device__ __half g_woh[(size_t)DD * DD];           // w_out [1024,1024]

// ---------------------------------------------------------------------------
// Helpers
// ---------------------------------------------------------------------------
__device__ __forceinline__ unsigned pack_h2(float lo, float hi) {
    unsigned u;
    asm("cvt.rn.f16x2.f32 %0, %1, %2;" : "=r"(u) : "f"(hi), "f"(lo));
    return u;
}

__device__ __forceinline__ void mma_f16(float* d, const unsigned* a,
                                        unsigned b0, unsigned b1) {
    asm volatile(
        "mma.sync.aligned.m16n8k16.row.col.f32.f16.f16.f32 "
        "{%0,%1,%2,%3}, {%4,%5,%6,%7}, {%8,%9}, {%0,%1,%2,%3};"
        : "+f"(d[0]), "+f"(d[1]), "+f"(d[2]), "+f"(d[3])
        : "r"(a[0]), "r"(a[1]), "r"(a[2]), "r"(a[3]), "r"(b0), "r"(b1));
}

__device__ __forceinline__ void ldsm4(unsigned* d, uint32_t addr) {
    asm volatile("ldmatrix.sync.aligned.m8n8.x4.shared.b16 {%0,%1,%2,%3}, [%4];"
                 : "=r"(d[0]), "=r"(d[1]), "=r"(d[2]), "=r"(d[3]) : "r"(addr));
}

__device__ __forceinline__ uint32_t smem_u32(const void* p) {
    uint32_t a;
    asm("{ .reg .u64 t; cvta.to.shared.u64 t, %1; cvt.u32.u64 %0, t; }"
        : "=r"(a) : "l"(p));
    return a;
}

__device__ __forceinline__ void cp_async16(uint32_t saddr, const void* gptr) {
    asm volatile("cp.async.cg.shared.global [%0], [%1], 16;"
                 :: "r"(saddr), "l"(gptr) : "memory");
}
__device__ __forceinline__ void cp_commit() {
    asm volatile("cp.async.commit_group;" ::: "memory");
}
template <int N>
__device__ __forceinline__ void cp_wait() {
    asm volatile("cp.async.wait_group %0;" :: "n"(N) : "memory");
}

// ---------------------------------------------------------------------------
// Kernel 1: adjacency
// ---------------------------------------------------------------------------
__global__ void adj_clear_k() {
    int i = blockIdx.x * blockDim.x + threadIdx.x;
    if (i < LL * (LL / 32)) g_adj[i] = 0u;
}

__global__ void adj_scatter_k(const int* __restrict__ edges) {
    int e = blockIdx.x * blockDim.x + threadIdx.x;
    if (e >= EE) return;
    int a = edges[2 * e + 0];
    int b = edges[2 * e + 1];
    atomicOr(&g_adj[a * 32 + (b >> 5)], 1u << (b & 31));
    atomicOr(&g_adj[b * 32 + (a >> 5)], 1u << (a & 31));
}

// ---------------------------------------------------------------------------
// Kernel 2: f32 -> f16 conversion (8 elements/thread)
// ---------------------------------------------------------------------------
__global__ void conv_f16_k(const float* __restrict__ in,
                           __half* __restrict__ out, int n8) {
    int i = blockIdx.x * blockDim.x + threadIdx.x;
    if (i >= n8) return;
    float4 a = ((const float4*)in)[2 * i];
    float4 b = ((const float4*)in)[2 * i + 1];
    ((uint4*)out)[i] = make_uint4(pack_h2(a.x, a.y), pack_h2(a.z, a.w),
                                  pack_h2(b.x, b.y), pack_h2(b.z, b.w));
}

// ---------------------------------------------------------------------------
// FP16 tensor-core GEMM v3 (m16n8k16, cp.async 2-stage, ldmatrix frags):
// C[m,n] = sum_k A[m,k]*B[n,k] + bias[n]
// BM=BN=128, BK=32, 8 warps, warp tile 64x32; fp32 accumulate.
// Smem rows 40 halves (80B): LDSM row-start banks {20r%32} disjoint.
// MODE 1: -> Q/K/V fp16 (V key-pair interleaved), q*0.125
// MODE 0: -> Cout f32 row-major (+bias)
// ---------------------------------------------------------------------------
#define GSTR 40                           // halves per smem row
#define GMATB (128 * GSTR * 2)            // bytes per matrix per stage (10240)
#define GSTGB (2 * GMATB)                 // bytes per stage (20480)

template <int MODE>
__global__ void __launch_bounds__(256, 2) gemm_k(const __half* __restrict__ A,
                                                 const __half* __restrict__ Bm,
                                                 const float* __restrict__ bias,
                                                 float* __restrict__ Cout) {
    constexpr int K = 1024;
    __shared__ char smc[2 * GSTGB];

    const int tid = threadIdx.x;
    const int m0 = blockIdx.y * 128;
    const int n0 = blockIdx.x * 128;

    // Staging: 2 threads/row, 16 halves (2x16B) each
    const int lrow = tid >> 1;
    const int lk   = (tid & 1) * 16;
    const __half* Ag = A  + (size_t)(m0 + lrow) * K + lk;
    const __half* Bg = Bm + (size_t)(n0 + lrow) * K + lk;
    const uint32_t sA = smem_u32(smc) + lrow * 80 + (tid & 1) * 32;

    const int wid  = tid >> 5;
    const int lane = tid & 31;
    const int wm   = (wid & 1) * 64;
    const int wn   = (wid >> 1) * 32;
    const int g    = lane >> 2;
    const int t    = lane & 3;

    // ldmatrix lane addressing
    const int matq = lane >> 3;            // which 8x8 matrix this lane feeds
    const int rin  = lane & 7;             // row within matrix
    uint32_t aBase[4], bBase[2];
    {
        const uint32_t smb = smem_u32(smc);
#pragma unroll
        for (int mi = 0; mi < 4; mi++)
            aBase[mi] = smb + (uint32_t)(wm + mi * 16 + (matq & 1) * 8 + rin) * 80
                            + (matq >> 1) * 16;
#pragma unroll
        for (int n2 = 0; n2 < 2; n2++)
            bBase[n2] = smb + GMATB
                            + (uint32_t)(wn + n2 * 16 + (matq >> 1) * 8 + rin) * 80
                            + (matq & 1) * 16;
    }

    float acc[4][4][4];
#pragma unroll
    for (int mi = 0; mi < 4; mi++)
#pragma unroll
        for (int ni = 0; ni < 4; ni++)
#pragma unroll
            for (int e = 0; e < 4; e++) acc[mi][ni][e] = 0.f;

    // Prologue: stage k-tiles 0,1
#pragma unroll
    for (int pt = 0; pt < 2; pt++) {
        const uint32_t base = sA + pt * GSTGB;
        cp_async16(base, Ag + pt * 32);
        cp_async16(base + 16, Ag + pt * 32 + 8);
        cp_async16(base + GMATB, Bg + pt * 32);
        cp_async16(base + GMATB + 16, Bg + pt * 32 + 8);
        cp_commit();
    }

#pragma unroll 1
    for (int it = 0; it < 32; it++) {
        const int s = it & 1;
        if (it < 31) cp_wait<1>(); else cp_wait<0>();
        __syncthreads();

        const uint32_t so = s * GSTGB;
#pragma unroll
        for (int ks = 0; ks < 2; ks++) {
            const uint32_t ko = so + ks * 32;
            unsigned af[4][4];
#pragma unroll
            for (int mi = 0; mi < 4; mi++) ldsm4(af[mi], aBase[mi] + ko);
            unsigned b0[4], b1[4];
#pragma unroll
            for (int n2 = 0; n2 < 2; n2++) {
                unsigned d[4];
                ldsm4(d, bBase[n2] + ko);
                b0[2 * n2]     = d[0];
                b1[2 * n2]     = d[1];
                b0[2 * n2 + 1] = d[2];
                b1[2 * n2 + 1] = d[3];
            }
#pragma unroll
            for (int mi = 0; mi < 4; mi++)
#pragma unroll
                for (int ni = 0; ni < 4; ni++)
                    mma_f16(acc[mi][ni], af[mi], b0[ni], b1[ni]);
        }

        __syncthreads();
        if (it + 2 < 32) {
            const uint32_t base = sA + s * GSTGB;
            const __half* ag = Ag + (it + 2) * 32;
            const __half* bg = Bg + (it + 2) * 32;
            cp_async16(base, ag);
            cp_async16(base + 16, ag + 8);
            cp_async16(base + GMATB, bg);
            cp_async16(base + GMATB + 16, bg + 8);
            cp_commit();
        }
    }

    const int g2t = 2 * t;
    if (MODE == 1) {
        const int part = n0 >> 10;     // 128-tile never crosses a 1024 boundary
        const float qs = (part == 0) ? 0.125f : 1.0f;
#pragma unroll
        for (int mi = 0; mi < 4; mi++) {
#pragma unroll
            for (int hf = 0; hf < 2; hf++) {
                const int m  = m0 + wm + mi * 16 + g + hf * 8;
                const int bb = m >> 10;
                const int ll = m & 1023;
#pragma unroll
                for (int ni = 0; ni < 4; ni++) {
                    const int col = n0 + wn + ni * 8 + g2t;
                    const int nn  = col & 1023;
                    const int h   = nn >> 6;
                    const int d   = nn & 63;
                    float v0 = (acc[mi][ni][hf * 2 + 0] + bias[col]) * qs;
                    float v1 = (acc[mi][ni][hf * 2 + 1] + bias[col + 1]) * qs;
                    if (part == 2) {
                        // V: key-pair interleaved [kp][d][2]
                        __half* vb = g_v + (((size_t)bb * HH + h) * (LL / 2) + (ll >> 1)) * 128 + (ll & 1);
                        vb[2 * d]       = __float2half_rn(v0);
                        vb[2 * (d + 1)] = __float2half_rn(v1);
                    } else {
                        __half* db = ((part == 0) ? g_q : g_k) +
                                     (((size_t)bb * HH + h) * LL + ll) * HD + d;
                        *(unsigned*)db = pack_h2(v0, v1);
                    }
                }
            }
        }
    } else {
#pragma unroll
        for (int mi = 0; mi < 4; mi++) {
#pragma unroll
            for (int hf = 0; hf < 2; hf++) {
                const int m = m0 + wm + mi * 16 + g + hf * 8;
#pragma unroll
                for (int ni = 0; ni < 4; ni++) {
                    const int col = n0 + wn + ni * 8 + g2t;
                    float* p = Cout + (size_t)m * DD + col;
                    p[0] = acc[mi][ni][hf * 2 + 0] + bias[col];
                    p[1] = acc[mi][ni][hf * 2 + 1] + bias[col + 1];
                }
            }
        }
    }
}

// ---------------------------------------------------------------------------
// Kernel 3: fp16 tensor-core masked flash attention, v6.
// v6: K fragments via ldmatrix.x4 (16 LDSM vs 64 LDS per tile).
// K smem: 64 rows x 144B (LDSM row banks {36r%32}=4r disjoint).
// V smem (key-pair interleaved): 32 rows x 288B, scalar frag loads.
// ---------------------------------------------------------------------------
#define KSB 9216                       // K tile bytes (64*144)
#define VSB 9216                       // V tile bytes (32*288)
#define STAGEB (KSB + VSB)             // 18432

__global__ void __launch_bounds__(256, 2) attn_mma_k() {
    __shared__ char sm[2 * STAGEB];

    const int bh   = blockIdx.y;
    const int tid  = threadIdx.x;
    const int wid  = tid >> 5;
    const int lane = tid & 31;
    const int g    = lane >> 2;
    const int t    = lane & 3;
    const int q0   = blockIdx.x * 128;
    const int wrow = wid * 16;

    const __half* Qg = g_q + (size_t)bh * LL * HD;
    const __half* Kg = g_k + (size_t)bh * LL * HD;
    const __half* Vg = g_v + (size_t)bh * (LL / 2) * 128;

    const int krow = tid >> 2;
    const __half* kg0 = Kg + (size_t)krow * HD + (tid & 3) * 16;
    const uint32_t kd0 = smem_u32(sm) + krow * 144 + (tid & 3) * 32;
    const int vrow = tid >> 3;
    const __half* vg0 = Vg + (size_t)vrow * 128 + (tid & 7) * 16;
    const uint32_t vd0 = smem_u32(sm) + KSB + vrow * 288 + (tid & 7) * 32;

    // ldmatrix lane addressing for K fragments
    const int matq = lane >> 3;
    const int rin  = lane & 7;
    uint32_t kBase[4];
#pragma unroll
    for (int n2 = 0; n2 < 4; n2++)
        kBase[n2] = smem_u32(sm) +
                    (uint32_t)(n2 * 16 + (matq >> 1) * 8 + rin) * 144 +
                    (matq & 1) * 16;

    unsigned qf[4][4];
    {
        const unsigned* Q0w = (const unsigned*)(Qg + (size_t)(q0 + wrow + g) * HD);
        const unsigned* Q1w = Q0w + 8 * (HD / 2);
#pragma unroll
        for (int ks = 0; ks < 4; ks++) {
            qf[ks][0] = Q0w[ks * 8 + t];
            qf[ks][1] = Q1w[ks * 8 + t];
            qf[ks][2] = Q0w[ks * 8 + t + 4];
            qf[ks][3] = Q1w[ks * 8 + t + 4];
        }
    }

#pragma unroll
    for (int it = 0; it < 2; it++) {
        const uint32_t soff = it * STAGEB;
        const size_t kgo = (size_t)it * 64 * HD;
        const size_t vgo = (size_t)it * 32 * 128;
        cp_async16(kd0 + soff, kg0 + kgo);
        cp_async16(kd0 + soff + 16, kg0 + kgo + 8);
        cp_async16(vd0 + soff, vg0 + vgo);
        cp_async16(vd0 + soff + 16, vg0 + vgo + 8);
        cp_commit();
    }

    float o[8][4];
#pragma unroll
    for (int nj = 0; nj < 8; nj++)
#pragma unroll
        for (int e = 0; e < 4; e++) o[nj][e] = 0.f;
    float m0 = NEGF, m1 = NEGF, l0 = 0.f, l1 = 0.f;

    const unsigned* adj0 = g_adj + (q0 + wrow + g) * 32;
    const unsigned* adj1 = adj0 + 8 * 32;

#pragma unroll 1
    for (int it = 0; it < 16; it++) {
        const int buf = it & 1;
        const int k0 = it * 64;
        if (it < 15) cp_wait<1>(); else cp_wait<0>();
        __syncthreads();

        const uint32_t kboff = buf * STAGEB;
        const unsigned* Vw = (const unsigned*)(sm + buf * STAGEB + KSB);

        float sa[8][4];
#pragma unroll
        for (int ni = 0; ni < 8; ni++)
#pragma unroll
            for (int e = 0; e < 4; e++) sa[ni][e] = 0.f;
#pragma unroll
        for (int ks = 0; ks < 4; ks++) {
            unsigned kb0[8], kb1[8];
#pragma unroll
            for (int n2 = 0; n2 < 4; n2++) {
                unsigned d[4];
                ldsm4(d, kBase[n2] + kboff + ks * 32);
                kb0[2 * n2]     = d[0];
                kb1[2 * n2]     = d[1];
                kb0[2 * n2 + 1] = d[2];
                kb1[2 * n2 + 1] = d[3];
            }
#pragma unroll
            for (int ni = 0; ni < 8; ni++)
                mma_f16(sa[ni], qf[ks], kb0[ni], kb1[ni]);
        }

        uint2 w0 = *(const uint2*)(adj0 + (k0 >> 5));
        uint2 w1 = *(const uint2*)(adj1 + (k0 >> 5));
        unsigned long long M0 = ((unsigned long long)w0.y << 32) | w0.x;
        unsigned long long M1 = ((unsigned long long)w1.y << 32) | w1.x;

        float tm0 = NEGF, tm1 = NEGF;
#pragma unroll
        for (int ni = 0; ni < 8; ni++) {
            const int c = ni * 8 + 2 * t;
            sa[ni][0] = ((M0 >> c) & 1ULL) ? NEGF : sa[ni][0];
            sa[ni][1] = ((M0 >> (c + 1)) & 1ULL) ? NEGF : sa[ni][1];
            sa[ni][2] = ((M1 >> c) & 1ULL) ? NEGF : sa[ni][2];
            sa[ni][3] = ((M1 >> (c + 1)) & 1ULL) ? NEGF : sa[ni][3];
            tm0 = fmaxf(tm0, fmaxf(sa[ni][0], sa[ni][1]));
            tm1 = fmaxf(tm1, fmaxf(sa[ni][2], sa[ni][3]));
        }
        tm0 = fmaxf(tm0, __shfl_xor_sync(0xffffffffu, tm0, 1));
        tm0 = fmaxf(tm0, __shfl_xor_sync(0xffffffffu, tm0, 2));
        tm1 = fmaxf(tm1, __shfl_xor_sync(0xffffffffu, tm1, 1));
        tm1 = fmaxf(tm1, __shfl_xor_sync(0xffffffffu, tm1, 2));

        const float mn0 = fmaxf(m0, tm0);
        const float mn1 = fmaxf(m1, tm1);
        const float sc0 = __expf(m0 - mn0);
        const float sc1 = __expf(m1 - mn1);
        m0 = mn0; m1 = mn1;

#pragma unroll
        for (int nj = 0; nj < 8; nj++) {
            o[nj][0] *= sc0; o[nj][1] *= sc0;
            o[nj][2] *= sc1; o[nj][3] *= sc1;
        }

        float rs0 = 0.f, rs1 = 0.f;
#pragma unroll
        for (int kb = 0; kb < 4; kb++) {
            const int nA = 2 * kb, nB = 2 * kb + 1;
            float pA0 = __expf(sa[nA][0] - mn0);
            float pA1 = __expf(sa[nA][1] - mn0);
            float pA2 = __expf(sa[nA][2] - mn1);
            float pA3 = __expf(sa[nA][3] - mn1);
            float pB0 = __expf(sa[nB][0] - mn0);
            float pB1 = __expf(sa[nB][1] - mn0);
            float pB2 = __expf(sa[nB][2] - mn1);
            float pB3 = __expf(sa[nB][3] - mn1);
            rs0 += pA0 + pA1 + pB0 + pB1;
            rs1 += pA2 + pA3 + pB2 + pB3;

            unsigned af[4];
            af[0] = pack_h2(pA0, pA1);
            af[1] = pack_h2(pA2, pA3);
            af[2] = pack_h2(pB0, pB1);
            af[3] = pack_h2(pB2, pB3);

            const unsigned* V0 = Vw + (kb * 8 + t) * 72;
            const unsigned* V1 = Vw + (kb * 8 + t + 4) * 72;
#pragma unroll
            for (int nj = 0; nj < 8; nj++)
                mma_f16(o[nj], af, V0[nj * 8 + g], V1[nj * 8 + g]);
        }
        rs0 += __shfl_xor_sync(0xffffffffu, rs0, 1);
        rs0 += __shfl_xor_sync(0xffffffffu, rs0, 2);
        rs1 += __shfl_xor_sync(0xffffffffu, rs1, 1);
        rs1 += __shfl_xor_sync(0xffffffffu, rs1, 2);
        l0 = l0 * sc0 + rs0;
        l1 = l1 * sc1 + rs1;

        __syncthreads();
        if (it + 2 < 16) {
            const uint32_t soff = buf * STAGEB;
            const size_t kgo = (size_t)(it + 2) * 64 * HD;
            const size_t vgo = (size_t)(it + 2) * 32 * 128;
            cp_async16(kd0 + soff, kg0 + kgo);
            cp_async16(kd0 + soff + 16, kg0 + kgo + 8);
            cp_async16(vd0 + soff, vg0 + vgo);
            cp_async16(vd0 + soff + 16, vg0 + vgo + 8);
            cp_commit();
        }
    }

    const float il0 = 1.f / l0;
    const float il1 = 1.f / l1;
    const int b = bh >> 4;
    const int h = bh & 15;
    const int qr0 = q0 + wrow + g;
    __half* out0 = g_attn + ((size_t)b * LL + qr0) * DD + h * HD;
    __half* out1 = g_attn + ((size_t)b * LL + qr0 + 8) * DD + h * HD;
#pragma unroll
    for (int nj = 0; nj < 8; nj++) {
        const int c = nj * 8 + 2 * t;
        *(unsigned*)(out0 + c) = pack_h2(o[nj][0] * il0, o[nj][1] * il0);
        *(unsigned*)(out1 + c) = pack_h2(o[nj][2] * il1, o[nj][3] * il1);
    }
}

// ---------------------------------------------------------------------------
// Launch
// ---------------------------------------------------------------------------
extern "C" void kernel_launch(void* const* d_in, const int* in_sizes, int n_in,
                              void* d_out, int out_size) {
    const float* x     = (const float*)d_in[0];   // [B,L,D]
    const int*   edges = (const int*)d_in[1];     // [E,2]
    const float* w_qkv = (const float*)d_in[2];   // [3D,D]
    const float* b_qkv = (const float*)d_in[3];   // [3D]
    const float* w_out = (const float*)d_in[4];   // [D,D]
    const float* b_out = (const float*)d_in[5];   // [D]
    float* out = (float*)d_out;                   // [B,L,D]

    __half* xh;  cudaGetSymbolAddress((void**)&xh, g_xh);
    __half* wqh; cudaGetSymbolAddress((void**)&wqh, g_wqh);
    __half* woh; cudaGetSymbolAddress((void**)&woh, g_woh);
    __half* ath; cudaGetSymbolAddress((void**)&ath, g_attn);

    // 1) adjacency + fp16 operand conversion
    adj_clear_k<<<(LL * 32 + 255) / 256, 256>>>();
    adj_scatter_k<<<(EE + 255) / 256, 256>>>(edges);
    conv_f16_k<<<(BB * LL * DD / 8 + 255) / 256, 256>>>(x, xh, BB * LL * DD / 8);
    conv_f16_k<<<(D3 * DD / 8 + 255) / 256, 256>>>(w_qkv, wqh, D3 * DD / 8);
    conv_f16_k<<<(DD * DD / 8 + 255) / 256, 256>>>(w_out, woh, DD * DD / 8);

    // 2) fused QKV projection (+bias, +q scaling, +head scatter) [fp16 TC]
    {
        dim3 grid(D3 / 128, (BB * LL) / 128);   // 24 x 32
        gemm_k<1><<<grid, 256>>>(xh, wqh, b_qkv, nullptr);
    }

    // 3) masked flash attention [fp16 TC, cp.async + ldmatrix]
    {
        dim3 grid(LL / 128, BB * HH);           // 8 x 64
        attn_mma_k<<<grid, 256>>>();
    }

    // 4) output projection (+bias) -> d_out [fp16 TC]
    {
        dim3 grid(DD / 128, (BB * LL) / 128);   // 8 x 32
        gemm_k<0><<<grid, 256>>>(ath, woh, b_out, out);
    }
}

// round 14
// speedup vs baseline: 2.1250x; 1.0193x over previous
#include <cuda_runtime.h>
#include <cuda_fp16.h>
#include <math.h>
#include <stdint.h>

// Problem constants
#define BB 4
#define LL 1024
#define DD 1024
#define HH 16
#define HD 64
#define EE 16384
#define D3 3072

#define NEGF (-1e30f)

// ---------------------------------------------------------------------------
// Scratch (static device globals; no allocation allowed)
// ---------------------------------------------------------------------------
__device__ __half g_q[(size_t)BB * HH * LL * HD];   // [B,H,L,HD] fp16, q*0.125
__device__ __half g_k[(size_t)BB * HH * LL * HD];   // [B,H,L,HD] fp16
__device__ __half g_v[(size_t)BB * HH * LL * HD];   // [B,H,L/2,64,2] key-pair interleaved
__device__ __half g_attn[(size_t)BB * LL * DD];     // [B,L,D] fp16
__device__ unsigned g_adj[LL * (LL / 32)];          // bitmask

// fp16 copies of f32 GEMM operands (converted once per launch)
__device__ __half g_xh[(size_t)BB * LL * DD];       // x     [4096,1024]
__device__ __half g_wqh[(size_t)D3 * DD];           // w_qkv [3072,1024]
__device__ __half g_woh[(size_t)DD * DD];           // w_out [1024,1024]

// ---------------------------------------------------------------------------
// Helpers
// ---------------------------------------------------------------------------
__device__ __forceinline__ unsigned pack_h2(float lo, float hi) {
    unsigned u;
    asm("cvt.rn.f16x2.f32 %0, %1, %2;" : "=r"(u) : "f"(hi), "f"(lo));
    return u;
}

__device__ __forceinline__ void mma_f16(float* d, const unsigned* a,
                                        unsigned b0, unsigned b1) {
    asm volatile(
        "mma.sync.aligned.m16n8k16.row.col.f32.f16.f16.f32 "
        "{%0,%1,%2,%3}, {%4,%5,%6,%7}, {%8,%9}, {%0,%1,%2,%3};"
        : "+f"(d[0]), "+f"(d[1]), "+f"(d[2]), "+f"(d[3])
        : "r"(a[0]), "r"(a[1]), "r"(a[2]), "r"(a[3]), "r"(b0), "r"(b1));
}

__device__ __forceinline__ void ldsm4(unsigned* d, uint32_t addr) {
    asm volatile("ldmatrix.sync.aligned.m8n8.x4.shared.b16 {%0,%1,%2,%3}, [%4];"
                 : "=r"(d[0]), "=r"(d[1]), "=r"(d[2]), "=r"(d[3]) : "r"(addr));
}

__device__ __forceinline__ uint32_t smem_u32(const void* p) {
    uint32_t a;
    asm("{ .reg .u64 t; cvta.to.shared.u64 t, %1; cvt.u32.u64 %0, t; }"
        : "=r"(a) : "l"(p));
    return a;
}

__device__ __forceinline__ void cp_async16(uint32_t saddr, const void* gptr) {
    asm volatile("cp.async.cg.shared.global [%0], [%1], 16;"
                 :: "r"(saddr), "l"(gptr) : "memory");
}
__device__ __forceinline__ void cp_commit() {
    asm volatile("cp.async.commit_group;" ::: "memory");
}
template <int N>
__device__ __forceinline__ void cp_wait() {
    asm volatile("cp.async.wait_group %0;" :: "n"(N) : "memory");
}

// ---------------------------------------------------------------------------
// Kernel 1: adjacency
// ---------------------------------------------------------------------------
__global__ void adj_clear_k() {
    int i = blockIdx.x * blockDim.x + threadIdx.x;
    if (i < LL * (LL / 32)) g_adj[i] = 0u;
}

__global__ void adj_scatter_k(const int* __restrict__ edges) {
    int e = blockIdx.x * blockDim.x + threadIdx.x;
    if (e >= EE) return;
    int a = edges[2 * e + 0];
    int b = edges[2 * e + 1];
    atomicOr(&g_adj[a * 32 + (b >> 5)], 1u << (b & 31));
    atomicOr(&g_adj[b * 32 + (a >> 5)], 1u << (a & 31));
}

// ---------------------------------------------------------------------------
// Kernel 2: fused f32 -> f16 conversion for x, w_qkv, w_out (8 elems/thread)
// ---------------------------------------------------------------------------
#define NX8 (BB * LL * DD / 8)
#define NQ8 (D3 * DD / 8)
#define NO8 (DD * DD / 8)

__global__ void conv_all_k(const float* __restrict__ x,
                           const float* __restrict__ wq,
                           const float* __restrict__ wo) {
    int i = blockIdx.x * blockDim.x + threadIdx.x;
    const float* src;
    __half* dst;
    int j;
    if (i < NX8) { src = x; dst = g_xh; j = i; }
    else if (i < NX8 + NQ8) { src = wq; dst = g_wqh; j = i - NX8; }
    else if (i < NX8 + NQ8 + NO8) { src = wo; dst = g_woh; j = i - NX8 - NQ8; }
    else return;
    float4 a = ((const float4*)src)[2 * j];
    float4 b = ((const float4*)src)[2 * j + 1];
    ((uint4*)dst)[j] = make_uint4(pack_h2(a.x, a.y), pack_h2(a.z, a.w),
                                  pack_h2(b.x, b.y), pack_h2(b.z, b.w));
}

// ---------------------------------------------------------------------------
// FP16 tensor-core GEMM v4 (m16n8k16, 4-stage cp.async ring, ldmatrix frags,
// ONE barrier per k-iter): C[m,n] = sum_k A[m,k]*B[n,k] + bias[n]
// BM=BN=128, BK=32, 8 warps, warp tile 64x32; fp32 accumulate.
// Smem rows 40 halves (80B); dynamic smem 4*20480 = 81920 B.
// MODE 1: -> Q/K/V fp16 (V key-pair interleaved), q*0.125
// MODE 0: -> Cout f32 row-major (+bias)
// ---------------------------------------------------------------------------
#define GSTR 40                           // halves per smem row
#define GMATB (128 * GSTR * 2)            // bytes per matrix per stage (10240)
#define GSTGB (2 * GMATB)                 // bytes per stage (20480)
#define GEMM_SMEM (4 * GSTGB)             // 81920 B

template <int MODE>
__global__ void __launch_bounds__(256, 2) gemm_k(const __half* __restrict__ A,
                                                 const __half* __restrict__ Bm,
                                                 const float* __restrict__ bias,
                                                 float* __restrict__ Cout) {
    constexpr int K = 1024;
    constexpr int NT = 32;                // k-tiles
    extern __shared__ char smc[];

    const int tid = threadIdx.x;
    const int m0 = blockIdx.y * 128;
    const int n0 = blockIdx.x * 128;

    // Staging: 2 threads/row, 16 halves (2x16B) each
    const int lrow = tid >> 1;
    const __half* Ag = A  + (size_t)(m0 + lrow) * K + (tid & 1) * 16;
    const __half* Bg = Bm + (size_t)(n0 + lrow) * K + (tid & 1) * 16;
    const uint32_t sA = smem_u32(smc) + lrow * 80 + (tid & 1) * 32;

    const int wid  = tid >> 5;
    const int lane = tid & 31;
    const int wm   = (wid & 1) * 64;
    const int wn   = (wid >> 1) * 32;
    const int g    = lane >> 2;
    const int t    = lane & 3;

    // ldmatrix lane addressing
    const int matq = lane >> 3;
    const int rin  = lane & 7;
    uint32_t aBase[4], bBase[2];
    {
        const uint32_t smb = smem_u32(smc);
#pragma unroll
        for (int mi = 0; mi < 4; mi++)
            aBase[mi] = smb + (uint32_t)(wm + mi * 16 + (matq & 1) * 8 + rin) * 80
                            + (matq >> 1) * 16;
#pragma unroll
        for (int n2 = 0; n2 < 2; n2++)
            bBase[n2] = smb + GMATB
                            + (uint32_t)(wn + n2 * 16 + (matq >> 1) * 8 + rin) * 80
                            + (matq & 1) * 16;
    }

    float acc[4][4][4];
#pragma unroll
    for (int mi = 0; mi < 4; mi++)
#pragma unroll
        for (int ni = 0; ni < 4; ni++)
#pragma unroll
            for (int e = 0; e < 4; e++) acc[mi][ni][e] = 0.f;

    // Prologue: stage k-tiles 0,1,2
#pragma unroll
    for (int pt = 0; pt < 3; pt++) {
        const uint32_t base = sA + pt * GSTGB;
        cp_async16(base, Ag + pt * 32);
        cp_async16(base + 16, Ag + pt * 32 + 8);
        cp_async16(base + GMATB, Bg + pt * 32);
        cp_async16(base + GMATB + 16, Bg + pt * 32 + 8);
        cp_commit();
    }

#pragma unroll 1
    for (int it = 0; it < NT; it++) {
        if (it < NT - 2) cp_wait<2>();
        else if (it == NT - 2) cp_wait<1>();
        else cp_wait<0>();
        __syncthreads();

        // Issue loads for tile it+3 into stage (it+3)&3 == (it-1)&3
        // (consumed at iter it-1; all threads past the sync above).
        if (it + 3 < NT) {
            const uint32_t base = sA + ((it + 3) & 3) * GSTGB;
            const __half* ag = Ag + (it + 3) * 32;
            const __half* bg = Bg + (it + 3) * 32;
            cp_async16(base, ag);
            cp_async16(base + 16, ag + 8);
            cp_async16(base + GMATB, bg);
            cp_async16(base + GMATB + 16, bg + 8);
            cp_commit();
        }

        const uint32_t so = (it & 3) * GSTGB;
#pragma unroll
        for (int ks = 0; ks < 2; ks++) {
            const uint32_t ko = so + ks * 32;
            unsigned af[4][4];
#pragma unroll
            for (int mi = 0; mi < 4; mi++) ldsm4(af[mi], aBase[mi] + ko);
            unsigned b0[4], b1[4];
#pragma unroll
            for (int n2 = 0; n2 < 2; n2++) {
                unsigned d[4];
                ldsm4(d, bBase[n2] + ko);
                b0[2 * n2]     = d[0];
                b1[2 * n2]     = d[1];
                b0[2 * n2 + 1] = d[2];
                b1[2 * n2 + 1] = d[3];
            }
#pragma unroll
            for (int mi = 0; mi < 4; mi++)
#pragma unroll
                for (int ni = 0; ni < 4; ni++)
                    mma_f16(acc[mi][ni], af[mi], b0[ni], b1[ni]);
        }
    }

    const int g2t = 2 * t;
    if (MODE == 1) {
        const int part = n0 >> 10;     // 128-tile never crosses a 1024 boundary
        const float qs = (part == 0) ? 0.125f : 1.0f;
#pragma unroll
        for (int mi = 0; mi < 4; mi++) {
#pragma unroll
            for (int hf = 0; hf < 2; hf++) {
                const int m  = m0 + wm + mi * 16 + g + hf * 8;
                const int bb = m >> 10;
                const int ll = m & 1023;
#pragma unroll
                for (int ni = 0; ni < 4; ni++) {
                    const int col = n0 + wn + ni * 8 + g2t;
                    const int nn  = col & 1023;
                    const int h   = nn >> 6;
                    const int d   = nn & 63;
                    float v0 = (acc[mi][ni][hf * 2 + 0] + bias[col]) * qs;
                    float v1 = (acc[mi][ni][hf * 2 + 1] + bias[col + 1]) * qs;
                    if (part == 2) {
                        // V: key-pair interleaved [kp][d][2]
                        __half* vb = g_v + (((size_t)bb * HH + h) * (LL / 2) + (ll >> 1)) * 128 + (ll & 1);
                        vb[2 * d]       = __float2half_rn(v0);
                        vb[2 * (d + 1)] = __float2half_rn(v1);
                    } else {
                        __half* db = ((part == 0) ? g_q : g_k) +
                                     (((size_t)bb * HH + h) * LL + ll) * HD + d;
                        *(unsigned*)db = pack_h2(v0, v1);
                    }
                }
            }
        }
    } else {
#pragma unroll
        for (int mi = 0; mi < 4; mi++) {
#pragma unroll
            for (int hf = 0; hf < 2; hf++) {
                const int m = m0 + wm + mi * 16 + g + hf * 8;
#pragma unroll
                for (int ni = 0; ni < 4; ni++) {
                    const int col = n0 + wn + ni * 8 + g2t;
                    float* p = Cout + (size_t)m * DD + col;
                    p[0] = acc[mi][ni][hf * 2 + 0] + bias[col];
                    p[1] = acc[mi][ni][hf * 2 + 1] + bias[col + 1];
                }
            }
        }
    }
}

// ---------------------------------------------------------------------------
// Kernel 3: fp16 tensor-core masked flash attention, v7.
// v7: 4-stage cp.async ring, ONE barrier per tile (was 2-stage, 2 barriers).
// K fragments via ldmatrix.x4; V key-pair interleaved, scalar frag loads.
// Dynamic smem 4*18432 = 73728 B; 2 CTAs/SM.
// ---------------------------------------------------------------------------
#define KSB 9216                       // K tile bytes (64*144)
#define VSB 9216                       // V tile bytes (32*288)
#define STAGEB (KSB + VSB)             // 18432
#define ATTN_SMEM (4 * STAGEB)         // 73728 B

__global__ void __launch_bounds__(256, 2) attn_mma_k() {
    extern __shared__ char sm[];
    constexpr int NT = 16;             // key tiles

    const int bh   = blockIdx.y;
    const int tid  = threadIdx.x;
    const int wid  = tid >> 5;
    const int lane = tid & 31;
    const int g    = lane >> 2;
    const int t    = lane & 3;
    const int q0   = blockIdx.x * 128;
    const int wrow = wid * 16;

    const __half* Qg = g_q + (size_t)bh * LL * HD;
    const __half* Kg = g_k + (size_t)bh * LL * HD;
    const __half* Vg = g_v + (size_t)bh * (LL / 2) * 128;

    const int krow = tid >> 2;
    const __half* kg0 = Kg + (size_t)krow * HD + (tid & 3) * 16;
    const uint32_t kd0 = smem_u32(sm) + krow * 144 + (tid & 3) * 32;
    const int vrow = tid >> 3;
    const __half* vg0 = Vg + (size_t)vrow * 128 + (tid & 7) * 16;
    const uint32_t vd0 = smem_u32(sm) + KSB + vrow * 288 + (tid & 7) * 32;

    // ldmatrix lane addressing for K fragments
    const int matq = lane >> 3;
    const int rin  = lane & 7;
    uint32_t kBase[4];
#pragma unroll
    for (int n2 = 0; n2 < 4; n2++)
        kBase[n2] = smem_u32(sm) +
                    (uint32_t)(n2 * 16 + (matq >> 1) * 8 + rin) * 144 +
                    (matq & 1) * 16;

    unsigned qf[4][4];
    {
        const unsigned* Q0w = (const unsigned*)(Qg + (size_t)(q0 + wrow + g) * HD);
        const unsigned* Q1w = Q0w + 8 * (HD / 2);
#pragma unroll
        for (int ks = 0; ks < 4; ks++) {
            qf[ks][0] = Q0w[ks * 8 + t];
            qf[ks][1] = Q1w[ks * 8 + t];
            qf[ks][2] = Q0w[ks * 8 + t + 4];
            qf[ks][3] = Q1w[ks * 8 + t + 4];
        }
    }

    // Prologue: stage tiles 0,1,2
#pragma unroll
    for (int it = 0; it < 3; it++) {
        const uint32_t soff = it * STAGEB;
        const size_t kgo = (size_t)it * 64 * HD;
        const size_t vgo = (size_t)it * 32 * 128;
        cp_async16(kd0 + soff, kg0 + kgo);
        cp_async16(kd0 + soff + 16, kg0 + kgo + 8);
        cp_async16(vd0 + soff, vg0 + vgo);
        cp_async16(vd0 + soff + 16, vg0 + vgo + 8);
        cp_commit();
    }

    float o[8][4];
#pragma unroll
    for (int nj = 0; nj < 8; nj++)
#pragma unroll
        for (int e = 0; e < 4; e++) o[nj][e] = 0.f;
    float m0 = NEGF, m1 = NEGF, l0 = 0.f, l1 = 0.f;

    const unsigned* adj0 = g_adj + (q0 + wrow + g) * 32;
    const unsigned* adj1 = adj0 + 8 * 32;

#pragma unroll 1
    for (int it = 0; it < NT; it++) {
        const int k0 = it * 64;
        if (it < NT - 2) cp_wait<2>();
        else if (it == NT - 2) cp_wait<1>();
        else cp_wait<0>();
        __syncthreads();

        // Restage tile it+3 into stage (it+3)&3 == (it-1)&3 (safe after sync)
        if (it + 3 < NT) {
            const uint32_t soff = ((it + 3) & 3) * STAGEB;
            const size_t kgo = (size_t)(it + 3) * 64 * HD;
            const size_t vgo = (size_t)(it + 3) * 32 * 128;
            cp_async16(kd0 + soff, kg0 + kgo);
            cp_async16(kd0 + soff + 16, kg0 + kgo + 8);
            cp_async16(vd0 + soff, vg0 + vgo);
            cp_async16(vd0 + soff + 16, vg0 + vgo + 8);
            cp_commit();
        }

        const uint32_t kboff = (it & 3) * STAGEB;
        const unsigned* Vw = (const unsigned*)(sm + (it & 3) * STAGEB + KSB);

        float sa[8][4];
#pragma unroll
        for (int ni = 0; ni < 8; ni++)
#pragma unroll
            for (int e = 0; e < 4; e++) sa[ni][e] = 0.f;
#pragma unroll
        for (int ks = 0; ks < 4; ks++) {
            unsigned kb0[8], kb1[8];
#pragma unroll
            for (int n2 = 0; n2 < 4; n2++) {
                unsigned d[4];
                ldsm4(d, kBase[n2] + kboff + ks * 32);
                kb0[2 * n2]     = d[0];
                kb1[2 * n2]     = d[1];
                kb0[2 * n2 + 1] = d[2];
                kb1[2 * n2 + 1] = d[3];
            }
#pragma unroll
            for (int ni = 0; ni < 8; ni++)
                mma_f16(sa[ni], qf[ks], kb0[ni], kb1[ni]);
        }

        uint2 w0 = *(const uint2*)(adj0 + (k0 >> 5));
        uint2 w1 = *(const uint2*)(adj1 + (k0 >> 5));
        unsigned long long M0 = ((unsigned long long)w0.y << 32) | w0.x;
        unsigned long long M1 = ((unsigned long long)w1.y << 32) | w1.x;

        float tm0 = NEGF, tm1 = NEGF;
#pragma unroll
        for (int ni = 0; ni < 8; ni++) {
            const int c = ni * 8 + 2 * t;
            sa[ni][0] = ((M0 >> c) & 1ULL) ? NEGF : sa[ni][0];
            sa[ni][1] = ((M0 >> (c + 1)) & 1ULL) ? NEGF : sa[ni][1];
            sa[ni][2] = ((M1 >> c) & 1ULL) ? NEGF : sa[ni][2];
            sa[ni][3] = ((M1 >> (c + 1)) & 1ULL) ? NEGF : sa[ni][3];
            tm0 = fmaxf(tm0, fmaxf(sa[ni][0], sa[ni][1]));
            tm1 = fmaxf(tm1, fmaxf(sa[ni][2], sa[ni][3]));
        }
        tm0 = fmaxf(tm0, __shfl_xor_sync(0xffffffffu, tm0, 1));
        tm0 = fmaxf(tm0, __shfl_xor_sync(0xffffffffu, tm0, 2));
        tm1 = fmaxf(tm1, __shfl_xor_sync(0xffffffffu, tm1, 1));
        tm1 = fmaxf(tm1, __shfl_xor_sync(0xffffffffu, tm1, 2));

        const float mn0 = fmaxf(m0, tm0);
        const float mn1 = fmaxf(m1, tm1);
        const float sc0 = __expf(m0 - mn0);
        const float sc1 = __expf(m1 - mn1);
        m0 = mn0; m1 = mn1;

#pragma unroll
        for (int nj = 0; nj < 8; nj++) {
            o[nj][0] *= sc0; o[nj][1] *= sc0;
            o[nj][2] *= sc1; o[nj][3] *= sc1;
        }

        float rs0 = 0.f, rs1 = 0.f;
#pragma unroll
        for (int kb = 0; kb < 4; kb++) {
            const int nA = 2 * kb, nB = 2 * kb + 1;
            float pA0 = __expf(sa[nA][0] - mn0);
            float pA1 = __expf(sa[nA][1] - mn0);
            float pA2 = __expf(sa[nA][2] - mn1);
            float pA3 = __expf(sa[nA][3] - mn1);
            float pB0 = __expf(sa[nB][0] - mn0);
            float pB1 = __expf(sa[nB][1] - mn0);
            float pB2 = __expf(sa[nB][2] - mn1);
            float pB3 = __expf(sa[nB][3] - mn1);
            rs0 += pA0 + pA1 + pB0 + pB1;
            rs1 += pA2 + pA3 + pB2 + pB3;

            unsigned af[4];
            af[0] = pack_h2(pA0, pA1);
            af[1] = pack_h2(pA2, pA3);
            af[2] = pack_h2(pB0, pB1);
            af[3] = pack_h2(pB2, pB3);

            const unsigned* V0 = Vw + (kb * 8 + t) * 72;
            const unsigned* V1 = Vw + (kb * 8 + t + 4) * 72;
#pragma unroll
            for (int nj = 0; nj < 8; nj++)
                mma_f16(o[nj], af, V0[nj * 8 + g], V1[nj * 8 + g]);
        }
        rs0 += __shfl_xor_sync(0xffffffffu, rs0, 1);
        rs0 += __shfl_xor_sync(0xffffffffu, rs0, 2);
        rs1 += __shfl_xor_sync(0xffffffffu, rs1, 1);
        rs1 += __shfl_xor_sync(0xffffffffu, rs1, 2);
        l0 = l0 * sc0 + rs0;
        l1 = l1 * sc1 + rs1;
    }

    const float il0 = 1.f / l0;
    const float il1 = 1.f / l1;
    const int b = bh >> 4;
    const int h = bh & 15;
    const int qr0 = q0 + wrow + g;
    __half* out0 = g_attn + ((size_t)b * LL + qr0) * DD + h * HD;
    __half* out1 = g_attn + ((size_t)b * LL + qr0 + 8) * DD + h * HD;
#pragma unroll
    for (int nj = 0; nj < 8; nj++) {
        const int c = nj * 8 + 2 * t;
        *(unsigned*)(out0 + c) = pack_h2(o[nj][0] * il0, o[nj][1] * il0);
        *(unsigned*)(out1 + c) = pack_h2(o[nj][2] * il1, o[nj][3] * il1);
    }
}

// ---------------------------------------------------------------------------
// Launch
// ---------------------------------------------------------------------------
extern "C" void kernel_launch(void* const* d_in, const int* in_sizes, int n_in,
                              void* d_out, int out_size) {
    const float* x     = (const float*)d_in[0];   // [B,L,D]
    const int*   edges = (const int*)d_in[1];     // [E,2]
    const float* w_qkv = (const float*)d_in[2];   // [3D,D]
    const float* b_qkv = (const float*)d_in[3];   // [3D]
    const float* w_out = (const float*)d_in[4];   // [D,D]
    const float* b_out = (const float*)d_in[5];   // [D]
    float* out = (float*)d_out;                   // [B,L,D]

    __half* xh;  cudaGetSymbolAddress((void**)&xh, g_xh);
    __half* wqh; cudaGetSymbolAddress((void**)&wqh, g_wqh);
    __half* woh; cudaGetSymbolAddress((void**)&woh, g_woh);
    __half* ath; cudaGetSymbolAddress((void**)&ath, g_attn);

    // >48KB dynamic smem (host attrs, capture-safe)
    cudaFuncSetAttribute(gemm_k<1>, cudaFuncAttributeMaxDynamicSharedMemorySize,
                         GEMM_SMEM);
    cudaFuncSetAttribute(gemm_k<0>, cudaFuncAttributeMaxDynamicSharedMemorySize,
                         GEMM_SMEM);
    cudaFuncSetAttribute(attn_mma_k, cudaFuncAttributeMaxDynamicSharedMemorySize,
                         ATTN_SMEM);

    // 1) adjacency + fused fp16 operand conversion
    adj_clear_k<<<(LL * 32 + 255) / 256, 256>>>();
    adj_scatter_k<<<(EE + 255) / 256, 256>>>(edges);
    conv_all_k<<<(NX8 + NQ8 + NO8 + 255) / 256, 256>>>(x, w_qkv, w_out);

    // 2) fused QKV projection (+bias, +q scaling, +head scatter) [fp16 TC]
    {
        dim3 grid(D3 / 128, (BB * LL) / 128);   // 24 x 32
        gemm_k<1><<<grid, 256, GEMM_SMEM>>>(xh, wqh, b_qkv, nullptr);
    }

    // 3) masked flash attention [fp16 TC, 4-stage cp.async + ldmatrix]
    {
        dim3 grid(LL / 128, BB * HH);           // 8 x 64
        attn_mma_k<<<grid, 256, ATTN_SMEM>>>();
    }

    // 4) output projection (+bias) -> d_out [fp16 TC]
    {
        dim3 grid(DD / 128, (BB * LL) / 128);   // 8 x 32
        gemm_k<0><<<grid, 256, GEMM_SMEM>>>(ath, woh, b_out, out);
    }
}